// round 1
// baseline (speedup 1.0000x reference)
#include <cuda_runtime.h>

#define NB 8
#define NS 2048
#define NF 256
#define NE 64
#define NDK 256
#define NIN 384

// Scratch for projected Q and K (16.8 MB each) — __device__ globals (no allocs).
__device__ float g_q[(size_t)NB * NS * NDK];
__device__ float g_k[(size_t)NB * NS * NDK];

// ---------------------------------------------------------------------------
// Kernel 1: Q/K projection.  C[16384, 256] = concat(seq,pos,time) @ W^T
// Grid: (m-tiles=256, n-tiles=4, z: 0=Q / 1=K), 256 threads, 64x64 tile,
// BK=32 (aligned to the 256/320/384 concat boundaries), 4x4 micro-tile.
// ---------------------------------------------------------------------------
__global__ __launch_bounds__(256) void proj_kernel(
    const float* __restrict__ seq,
    const float* __restrict__ pos,
    const float* __restrict__ tim,
    const float* __restrict__ Wq,
    const float* __restrict__ Wk)
{
    __shared__ float A_s[64][33];
    __shared__ float B_s[64][33];

    const float* W   = blockIdx.z ? Wk : Wq;
    float*       dst = blockIdx.z ? g_k : g_q;
    const int m0 = blockIdx.x * 64;
    const int n0 = blockIdx.y * 64;
    const int tid = threadIdx.x;
    const int ty = tid >> 4, tx = tid & 15;

    float acc[4][4] = {};

    for (int kt = 0; kt < 12; ++kt) {
        const float* src; int width, colbase;
        if (kt < 8)       { src = seq; width = NF; colbase = kt * 32; }
        else if (kt < 10) { src = pos; width = NE; colbase = (kt - 8) * 32; }
        else              { src = tim; width = NE; colbase = (kt - 10) * 32; }
        const int k0 = kt * 32;

        __syncthreads();
#pragma unroll
        for (int l = 0; l < 2; ++l) {
            int idx = tid + l * 256;
            int r = idx >> 3, c4 = idx & 7;
            float4 a = *(const float4*)(src + (size_t)(m0 + r) * width + colbase + c4 * 4);
            A_s[r][c4 * 4 + 0] = a.x; A_s[r][c4 * 4 + 1] = a.y;
            A_s[r][c4 * 4 + 2] = a.z; A_s[r][c4 * 4 + 3] = a.w;
            float4 w = *(const float4*)(W + (size_t)(n0 + r) * NIN + k0 + c4 * 4);
            B_s[r][c4 * 4 + 0] = w.x; B_s[r][c4 * 4 + 1] = w.y;
            B_s[r][c4 * 4 + 2] = w.z; B_s[r][c4 * 4 + 3] = w.w;
        }
        __syncthreads();

#pragma unroll 8
        for (int k = 0; k < 32; ++k) {
            float a0 = A_s[ty][k], a1 = A_s[ty + 16][k];
            float a2 = A_s[ty + 32][k], a3 = A_s[ty + 48][k];
            float b0 = B_s[tx][k], b1 = B_s[tx + 16][k];
            float b2 = B_s[tx + 32][k], b3 = B_s[tx + 48][k];
            acc[0][0] += a0 * b0; acc[0][1] += a0 * b1; acc[0][2] += a0 * b2; acc[0][3] += a0 * b3;
            acc[1][0] += a1 * b0; acc[1][1] += a1 * b1; acc[1][2] += a1 * b2; acc[1][3] += a1 * b3;
            acc[2][0] += a2 * b0; acc[2][1] += a2 * b1; acc[2][2] += a2 * b2; acc[2][3] += a2 * b3;
            acc[3][0] += a3 * b0; acc[3][1] += a3 * b1; acc[3][2] += a3 * b2; acc[3][3] += a3 * b3;
        }
    }

#pragma unroll
    for (int i = 0; i < 4; ++i) {
        int m = m0 + ty + 16 * i;
#pragma unroll
        for (int j = 0; j < 4; ++j)
            dst[(size_t)m * NDK + n0 + tx + 16 * j] = acc[i][j];
    }
}

// ---------------------------------------------------------------------------
// Kernel 2: fused attention.  One CTA = (batch b, 64-query tile).
// For each 64-key tile (starting at the diagonal when causal — triu keeps
// j >= i): S = Q K^T / 16, clamp to 10, mask = cluster>0 && (j>=i),
// p = exp(s) (no max-subtraction needed: s <= 10), accumulate O += p*V and
// den += p.  Divide at the end.
// ---------------------------------------------------------------------------
#define SMEM_FLOATS (64 * 257 * 2 + 64 * 256 + 64 * 65 + 64)
#define SMEM_BYTES  (SMEM_FLOATS * 4)

__global__ __launch_bounds__(256, 1) void attn_kernel(
    const float* __restrict__ seq,
    const float* __restrict__ cmask,
    const int*   __restrict__ causality,
    float* __restrict__ out)
{
    extern __shared__ float sm[];
    float* Q_s   = sm;                 // [64][257]  (row pad 1 -> conflict-light)
    float* K_s   = Q_s + 64 * 257;     // [64][257]
    float* V_s   = K_s + 64 * 257;     // [64][256]
    float* P_s   = V_s + 64 * 256;     // [65-stride, indexed P_s[k*65 + q]]
    float* den_s = P_s + 64 * 65;      // [64]

    const int qt  = blockIdx.x;        // query tile 0..31 (heavy tiles first)
    const int b   = blockIdx.y;
    const int q0  = qt * 64;
    const int tid = threadIdx.x;
    const int ty  = tid >> 4, tx = tid & 15;
    const int causal = causality[0];

    // Load Q tile once (64 x 256)
    const float* qsrc = g_q + ((size_t)b * NS + q0) * NDK;
#pragma unroll
    for (int l = 0; l < 16; ++l) {
        int idx = tid + l * 256;
        int r = idx >> 6, c4 = idx & 63;
        float4 v = *(const float4*)(qsrc + r * NDK + c4 * 4);
        float* p = Q_s + r * 257 + c4 * 4;
        p[0] = v.x; p[1] = v.y; p[2] = v.z; p[3] = v.w;
    }
    if (tid < 64) den_s[tid] = 0.f;

    float o[4][16];
#pragma unroll
    for (int i = 0; i < 4; ++i)
#pragma unroll
        for (int c = 0; c < 16; ++c) o[i][c] = 0.f;

    const int kt0 = causal ? qt : 0;
    for (int kt = kt0; kt < 32; ++kt) {
        const int k0 = kt * 64;
        __syncthreads();  // protect K_s/V_s/P_s from previous iteration readers

        const float* ksrc = g_k + ((size_t)b * NS + k0) * NDK;
        const float* vsrc = seq + ((size_t)b * NS + k0) * NF;
#pragma unroll
        for (int l = 0; l < 16; ++l) {
            int idx = tid + l * 256;
            int r = idx >> 6, c4 = idx & 63;
            float4 kv = *(const float4*)(ksrc + r * NDK + c4 * 4);
            float* p = K_s + r * 257 + c4 * 4;
            p[0] = kv.x; p[1] = kv.y; p[2] = kv.z; p[3] = kv.w;
            float4 vv = *(const float4*)(vsrc + r * NF + c4 * 4);
            *(float4*)(V_s + r * 256 + c4 * 4) = vv;
        }

        // Prefetch mask tile into registers (latency hidden behind phase A)
        float mreg[4][4];
        const float* mbase = cmask + (size_t)b * NS * NS + (size_t)q0 * NS + k0;
#pragma unroll
        for (int i = 0; i < 4; ++i)
#pragma unroll
            for (int j = 0; j < 4; ++j)
                mreg[i][j] = mbase[(size_t)(ty + 16 * i) * NS + tx + 16 * j];
        __syncthreads();

        // ---- Phase A: S = Q K^T (4x4 micro-tile, contraction over d=256)
        float sacc[4][4] = {};
#pragma unroll 8
        for (int d = 0; d < 256; ++d) {
            float a0 = Q_s[(ty)      * 257 + d];
            float a1 = Q_s[(ty + 16) * 257 + d];
            float a2 = Q_s[(ty + 32) * 257 + d];
            float a3 = Q_s[(ty + 48) * 257 + d];
            float b0 = K_s[(tx)      * 257 + d];
            float b1 = K_s[(tx + 16) * 257 + d];
            float b2 = K_s[(tx + 32) * 257 + d];
            float b3 = K_s[(tx + 48) * 257 + d];
            sacc[0][0] += a0 * b0; sacc[0][1] += a0 * b1; sacc[0][2] += a0 * b2; sacc[0][3] += a0 * b3;
            sacc[1][0] += a1 * b0; sacc[1][1] += a1 * b1; sacc[1][2] += a1 * b2; sacc[1][3] += a1 * b3;
            sacc[2][0] += a2 * b0; sacc[2][1] += a2 * b1; sacc[2][2] += a2 * b2; sacc[2][3] += a2 * b3;
            sacc[3][0] += a3 * b0; sacc[3][1] += a3 * b1; sacc[3][2] += a3 * b2; sacc[3][3] += a3 * b3;
        }

        // scale, clamp(<=10), mask, exp -> P_s[k][q]
#pragma unroll
        for (int i = 0; i < 4; ++i) {
            int q = q0 + ty + 16 * i;
#pragma unroll
            for (int j = 0; j < 4; ++j) {
                int k = k0 + tx + 16 * j;
                float s = fminf(sacc[i][j] * 0.0625f, 10.f);
                bool ok = (mreg[i][j] > 0.f) && (!causal || (k >= q));
                float p = ok ? __expf(s) : 0.f;
                P_s[(tx + 16 * j) * 65 + ty + 16 * i] = p;
            }
        }
        __syncthreads();

        // denominator: thread q (<64) owns den_s[q]
        if (tid < 64) {
            float dsum = 0.f;
#pragma unroll 16
            for (int k = 0; k < 64; ++k) dsum += P_s[k * 65 + tid];
            den_s[tid] += dsum;
        }

        // ---- Phase B: O += P @ V (thread = 4 q-rows x 16 f-cols)
#pragma unroll 2
        for (int k = 0; k < 64; ++k) {
            float p0 = P_s[k * 65 + ty];
            float p1 = P_s[k * 65 + ty + 16];
            float p2 = P_s[k * 65 + ty + 32];
            float p3 = P_s[k * 65 + ty + 48];
#pragma unroll
            for (int r = 0; r < 4; ++r) {
                float4 v = *(const float4*)(V_s + k * 256 + tx * 4 + 64 * r);
                o[0][r * 4 + 0] += p0 * v.x; o[0][r * 4 + 1] += p0 * v.y;
                o[0][r * 4 + 2] += p0 * v.z; o[0][r * 4 + 3] += p0 * v.w;
                o[1][r * 4 + 0] += p1 * v.x; o[1][r * 4 + 1] += p1 * v.y;
                o[1][r * 4 + 2] += p1 * v.z; o[1][r * 4 + 3] += p1 * v.w;
                o[2][r * 4 + 0] += p2 * v.x; o[2][r * 4 + 1] += p2 * v.y;
                o[2][r * 4 + 2] += p2 * v.z; o[2][r * 4 + 3] += p2 * v.w;
                o[3][r * 4 + 0] += p3 * v.x; o[3][r * 4 + 1] += p3 * v.y;
                o[3][r * 4 + 2] += p3 * v.z; o[3][r * 4 + 3] += p3 * v.w;
            }
        }
    }

    __syncthreads();  // den_s final before cross-thread read
    float* obase = out + ((size_t)b * NS + q0) * NF;
#pragma unroll
    for (int i = 0; i < 4; ++i) {
        float inv = 1.0f / den_s[ty + 16 * i];
#pragma unroll
        for (int r = 0; r < 4; ++r) {
            float4 v;
            v.x = o[i][r * 4 + 0] * inv;
            v.y = o[i][r * 4 + 1] * inv;
            v.z = o[i][r * 4 + 2] * inv;
            v.w = o[i][r * 4 + 3] * inv;
            *(float4*)(obase + (ty + 16 * i) * NF + tx * 4 + 64 * r) = v;
        }
    }
}

// ---------------------------------------------------------------------------
extern "C" void kernel_launch(void* const* d_in, const int* in_sizes, int n_in,
                              void* d_out, int out_size)
{
    const float* seq  = (const float*)d_in[0];
    const float* pos  = (const float*)d_in[1];
    const float* tim  = (const float*)d_in[2];
    const float* Wq   = (const float*)d_in[3];
    const float* Wk   = (const float*)d_in[4];
    const float* cm   = (const float*)d_in[5];
    const int*   caus = (const int*)d_in[6];
    float* out = (float*)d_out;

    cudaFuncSetAttribute(attn_kernel,
                         cudaFuncAttributeMaxDynamicSharedMemorySize, SMEM_BYTES);

    dim3 gp(NB * NS / 64, NDK / 64, 2);  // (256, 4, 2)
    proj_kernel<<<gp, 256>>>(seq, pos, tim, Wq, Wk);

    dim3 ga(NS / 64, NB);                // (32, 8): heaviest q-tiles launch first
    attn_kernel<<<ga, 256, SMEM_BYTES>>>(seq, cm, caus, out);
}

// round 2
// speedup vs baseline: 1.6372x; 1.6372x over previous
#include <cuda_runtime.h>

#define NB 8
#define NS 2048
#define NF 256
#define NE 64
#define NDK 256
#define NIN 384

// Scratch for projected Q and K (16.8 MB each) — __device__ globals (no allocs).
__device__ float g_q[(size_t)NB * NS * NDK];
__device__ float g_k[(size_t)NB * NS * NDK];

// ---------------------------------------------------------------------------
// Kernel 1: Q/K projection.  C[16384, 256] = concat(seq,pos,time) @ W^T
// Grid: (m-tiles=256, n-tiles=4, z: 0=Q / 1=K), 256 threads, 64x64 tile,
// BK=32 (aligned to the 256/320/384 concat boundaries), 4x4 micro-tile.
// ---------------------------------------------------------------------------
__global__ __launch_bounds__(256) void proj_kernel(
    const float* __restrict__ seq,
    const float* __restrict__ pos,
    const float* __restrict__ tim,
    const float* __restrict__ Wq,
    const float* __restrict__ Wk)
{
    __shared__ float A_s[64][33];
    __shared__ float B_s[64][33];

    const float* W   = blockIdx.z ? Wk : Wq;
    float*       dst = blockIdx.z ? g_k : g_q;
    const int m0 = blockIdx.x * 64;
    const int n0 = blockIdx.y * 64;
    const int tid = threadIdx.x;
    const int ty = tid >> 4, tx = tid & 15;

    float acc[4][4] = {};

    for (int kt = 0; kt < 12; ++kt) {
        const float* src; int width, colbase;
        if (kt < 8)       { src = seq; width = NF; colbase = kt * 32; }
        else if (kt < 10) { src = pos; width = NE; colbase = (kt - 8) * 32; }
        else              { src = tim; width = NE; colbase = (kt - 10) * 32; }
        const int k0 = kt * 32;

        __syncthreads();
#pragma unroll
        for (int l = 0; l < 2; ++l) {
            int idx = tid + l * 256;
            int r = idx >> 3, c4 = idx & 7;
            float4 a = *(const float4*)(src + (size_t)(m0 + r) * width + colbase + c4 * 4);
            A_s[r][c4 * 4 + 0] = a.x; A_s[r][c4 * 4 + 1] = a.y;
            A_s[r][c4 * 4 + 2] = a.z; A_s[r][c4 * 4 + 3] = a.w;
            float4 w = *(const float4*)(W + (size_t)(n0 + r) * NIN + k0 + c4 * 4);
            B_s[r][c4 * 4 + 0] = w.x; B_s[r][c4 * 4 + 1] = w.y;
            B_s[r][c4 * 4 + 2] = w.z; B_s[r][c4 * 4 + 3] = w.w;
        }
        __syncthreads();

#pragma unroll 8
        for (int k = 0; k < 32; ++k) {
            float a0 = A_s[ty][k], a1 = A_s[ty + 16][k];
            float a2 = A_s[ty + 32][k], a3 = A_s[ty + 48][k];
            float b0 = B_s[tx][k], b1 = B_s[tx + 16][k];
            float b2 = B_s[tx + 32][k], b3 = B_s[tx + 48][k];
            acc[0][0] += a0 * b0; acc[0][1] += a0 * b1; acc[0][2] += a0 * b2; acc[0][3] += a0 * b3;
            acc[1][0] += a1 * b0; acc[1][1] += a1 * b1; acc[1][2] += a1 * b2; acc[1][3] += a1 * b3;
            acc[2][0] += a2 * b0; acc[2][1] += a2 * b1; acc[2][2] += a2 * b2; acc[2][3] += a2 * b3;
            acc[3][0] += a3 * b0; acc[3][1] += a3 * b1; acc[3][2] += a3 * b2; acc[3][3] += a3 * b3;
        }
    }

#pragma unroll
    for (int i = 0; i < 4; ++i) {
        int m = m0 + ty + 16 * i;
#pragma unroll
        for (int j = 0; j < 4; ++j)
            dst[(size_t)m * NDK + n0 + tx + 16 * j] = acc[i][j];
    }
}

// ---------------------------------------------------------------------------
// Kernel 2: fused attention.  One CTA = (batch b, 64-query tile).
// For each 64-key tile (starting at the diagonal when causal — triu keeps
// j >= i): S = Q K^T / 16, clamp to 10, mask = cluster>0 && (j>=i),
// p = exp(s) (no max-subtraction needed: s <= 10), accumulate O += p*V and
// den += p.  Divide at the end.
// ---------------------------------------------------------------------------
#define SMEM_FLOATS (64 * 257 * 2 + 64 * 256 + 64 * 65 + 64)
#define SMEM_BYTES  (SMEM_FLOATS * 4)

__global__ __launch_bounds__(256, 1) void attn_kernel(
    const float* __restrict__ seq,
    const float* __restrict__ cmask,
    const int*   __restrict__ causality,
    float* __restrict__ out)
{
    extern __shared__ float sm[];
    float* Q_s   = sm;                 // [64][257]  (row pad 1 -> conflict-light)
    float* K_s   = Q_s + 64 * 257;     // [64][257]
    float* V_s   = K_s + 64 * 257;     // [64][256]
    float* P_s   = V_s + 64 * 256;     // [65-stride, indexed P_s[k*65 + q]]
    float* den_s = P_s + 64 * 65;      // [64]

    const int qt  = blockIdx.x;        // query tile 0..31 (heavy tiles first)
    const int b   = blockIdx.y;
    const int q0  = qt * 64;
    const int tid = threadIdx.x;
    const int ty  = tid >> 4, tx = tid & 15;
    const int causal = causality[0];

    // Load Q tile once (64 x 256)
    const float* qsrc = g_q + ((size_t)b * NS + q0) * NDK;
#pragma unroll
    for (int l = 0; l < 16; ++l) {
        int idx = tid + l * 256;
        int r = idx >> 6, c4 = idx & 63;
        float4 v = *(const float4*)(qsrc + r * NDK + c4 * 4);
        float* p = Q_s + r * 257 + c4 * 4;
        p[0] = v.x; p[1] = v.y; p[2] = v.z; p[3] = v.w;
    }
    if (tid < 64) den_s[tid] = 0.f;

    float o[4][16];
#pragma unroll
    for (int i = 0; i < 4; ++i)
#pragma unroll
        for (int c = 0; c < 16; ++c) o[i][c] = 0.f;

    const int kt0 = causal ? qt : 0;
    for (int kt = kt0; kt < 32; ++kt) {
        const int k0 = kt * 64;
        __syncthreads();  // protect K_s/V_s/P_s from previous iteration readers

        const float* ksrc = g_k + ((size_t)b * NS + k0) * NDK;
        const float* vsrc = seq + ((size_t)b * NS + k0) * NF;
#pragma unroll
        for (int l = 0; l < 16; ++l) {
            int idx = tid + l * 256;
            int r = idx >> 6, c4 = idx & 63;
            float4 kv = *(const float4*)(ksrc + r * NDK + c4 * 4);
            float* p = K_s + r * 257 + c4 * 4;
            p[0] = kv.x; p[1] = kv.y; p[2] = kv.z; p[3] = kv.w;
            float4 vv = *(const float4*)(vsrc + r * NF + c4 * 4);
            *(float4*)(V_s + r * 256 + c4 * 4) = vv;
        }

        // Prefetch mask tile into registers (latency hidden behind phase A)
        float mreg[4][4];
        const float* mbase = cmask + (size_t)b * NS * NS + (size_t)q0 * NS + k0;
#pragma unroll
        for (int i = 0; i < 4; ++i)
#pragma unroll
            for (int j = 0; j < 4; ++j)
                mreg[i][j] = mbase[(size_t)(ty + 16 * i) * NS + tx + 16 * j];
        __syncthreads();

        // ---- Phase A: S = Q K^T (4x4 micro-tile, contraction over d=256)
        float sacc[4][4] = {};
#pragma unroll 8
        for (int d = 0; d < 256; ++d) {
            float a0 = Q_s[(ty)      * 257 + d];
            float a1 = Q_s[(ty + 16) * 257 + d];
            float a2 = Q_s[(ty + 32) * 257 + d];
            float a3 = Q_s[(ty + 48) * 257 + d];
            float b0 = K_s[(tx)      * 257 + d];
            float b1 = K_s[(tx + 16) * 257 + d];
            float b2 = K_s[(tx + 32) * 257 + d];
            float b3 = K_s[(tx + 48) * 257 + d];
            sacc[0][0] += a0 * b0; sacc[0][1] += a0 * b1; sacc[0][2] += a0 * b2; sacc[0][3] += a0 * b3;
            sacc[1][0] += a1 * b0; sacc[1][1] += a1 * b1; sacc[1][2] += a1 * b2; sacc[1][3] += a1 * b3;
            sacc[2][0] += a2 * b0; sacc[2][1] += a2 * b1; sacc[2][2] += a2 * b2; sacc[2][3] += a2 * b3;
            sacc[3][0] += a3 * b0; sacc[3][1] += a3 * b1; sacc[3][2] += a3 * b2; sacc[3][3] += a3 * b3;
        }

        // scale, clamp(<=10), mask, exp -> P_s[k][q]
#pragma unroll
        for (int i = 0; i < 4; ++i) {
            int q = q0 + ty + 16 * i;
#pragma unroll
            for (int j = 0; j < 4; ++j) {
                int k = k0 + tx + 16 * j;
                float s = fminf(sacc[i][j] * 0.0625f, 10.f);
                bool ok = (mreg[i][j] > 0.f) && (!causal || (k >= q));
                float p = ok ? __expf(s) : 0.f;
                P_s[(tx + 16 * j) * 65 + ty + 16 * i] = p;
            }
        }
        __syncthreads();

        // denominator: thread q (<64) owns den_s[q]
        if (tid < 64) {
            float dsum = 0.f;
#pragma unroll 16
            for (int k = 0; k < 64; ++k) dsum += P_s[k * 65 + tid];
            den_s[tid] += dsum;
        }

        // ---- Phase B: O += P @ V (thread = 4 q-rows x 16 f-cols)
#pragma unroll 2
        for (int k = 0; k < 64; ++k) {
            float p0 = P_s[k * 65 + ty];
            float p1 = P_s[k * 65 + ty + 16];
            float p2 = P_s[k * 65 + ty + 32];
            float p3 = P_s[k * 65 + ty + 48];
#pragma unroll
            for (int r = 0; r < 4; ++r) {
                float4 v = *(const float4*)(V_s + k * 256 + tx * 4 + 64 * r);
                o[0][r * 4 + 0] += p0 * v.x; o[0][r * 4 + 1] += p0 * v.y;
                o[0][r * 4 + 2] += p0 * v.z; o[0][r * 4 + 3] += p0 * v.w;
                o[1][r * 4 + 0] += p1 * v.x; o[1][r * 4 + 1] += p1 * v.y;
                o[1][r * 4 + 2] += p1 * v.z; o[1][r * 4 + 3] += p1 * v.w;
                o[2][r * 4 + 0] += p2 * v.x; o[2][r * 4 + 1] += p2 * v.y;
                o[2][r * 4 + 2] += p2 * v.z; o[2][r * 4 + 3] += p2 * v.w;
                o[3][r * 4 + 0] += p3 * v.x; o[3][r * 4 + 1] += p3 * v.y;
                o[3][r * 4 + 2] += p3 * v.z; o[3][r * 4 + 3] += p3 * v.w;
            }
        }
    }

    __syncthreads();  // den_s final before cross-thread read
    float* obase = out + ((size_t)b * NS + q0) * NF;
#pragma unroll
    for (int i = 0; i < 4; ++i) {
        float inv = 1.0f / den_s[ty + 16 * i];
#pragma unroll
        for (int r = 0; r < 4; ++r) {
            float4 v;
            v.x = o[i][r * 4 + 0] * inv;
            v.y = o[i][r * 4 + 1] * inv;
            v.z = o[i][r * 4 + 2] * inv;
            v.w = o[i][r * 4 + 3] * inv;
            *(float4*)(obase + (ty + 16 * i) * NF + tx * 4 + 64 * r) = v;
        }
    }
}

// ---------------------------------------------------------------------------
extern "C" void kernel_launch(void* const* d_in, const int* in_sizes, int n_in,
                              void* d_out, int out_size)
{
    const float* seq  = (const float*)d_in[0];
    const float* pos  = (const float*)d_in[1];
    const float* tim  = (const float*)d_in[2];
    const float* Wq   = (const float*)d_in[3];
    const float* Wk   = (const float*)d_in[4];
    const float* cm   = (const float*)d_in[5];
    const int*   caus = (const int*)d_in[6];
    float* out = (float*)d_out;

    cudaFuncSetAttribute(attn_kernel,
                         cudaFuncAttributeMaxDynamicSharedMemorySize, SMEM_BYTES);

    dim3 gp(NB * NS / 64, NDK / 64, 2);  // (256, 4, 2)
    proj_kernel<<<gp, 256>>>(seq, pos, tim, Wq, Wk);

    dim3 ga(NS / 64, NB);                // (32, 8): heaviest q-tiles launch first
    attn_kernel<<<ga, 256, SMEM_BYTES>>>(seq, cm, caus, out);
}

// round 3
// speedup vs baseline: 2.4461x; 1.4941x over previous
#include <cuda_runtime.h>

#define NB 8
#define NS 2048
#define NF 256
#define NE 64
#define NDK 256
#define NIN 384

// Scratch for projected Q and K — __device__ globals (no allocs).
__device__ float g_q[(size_t)NB * NS * NDK];
__device__ float g_k[(size_t)NB * NS * NDK];

// ---------------------------------------------------------------------------
// Kernel 1: Q/K projection.  C[16384,256] = concat(seq,pos,time) @ W^T
// 64x64 tile, BK=32, 4x4 micro-tile, float4 LDS (row stride 36 => 4 mod 32,
// conflict-free 128-bit shared loads).
// ---------------------------------------------------------------------------
#define PSTR 36

__global__ __launch_bounds__(256) void proj_kernel(
    const float* __restrict__ seq,
    const float* __restrict__ pos,
    const float* __restrict__ tim,
    const float* __restrict__ Wq,
    const float* __restrict__ Wk)
{
    __shared__ float A_s[64 * PSTR];
    __shared__ float B_s[64 * PSTR];

    const float* W   = blockIdx.z ? Wk : Wq;
    float*       dst = blockIdx.z ? g_k : g_q;
    const int m0 = blockIdx.x * 64;
    const int n0 = blockIdx.y * 64;
    const int tid = threadIdx.x;
    const int ty = tid >> 4, tx = tid & 15;

    float acc[4][4] = {};

    for (int kt = 0; kt < 12; ++kt) {
        const float* src; int width, colbase;
        if (kt < 8)       { src = seq; width = NF; colbase = kt * 32; }
        else if (kt < 10) { src = pos; width = NE; colbase = (kt - 8) * 32; }
        else              { src = tim; width = NE; colbase = (kt - 10) * 32; }
        const int k0 = kt * 32;

        __syncthreads();
#pragma unroll
        for (int l = 0; l < 2; ++l) {
            int idx = tid + l * 256;
            int r = idx >> 3, c4 = idx & 7;
            float4 a = *(const float4*)(src + (size_t)(m0 + r) * width + colbase + c4 * 4);
            float* pa = A_s + r * PSTR + c4 * 4;
            pa[0] = a.x; pa[1] = a.y; pa[2] = a.z; pa[3] = a.w;
            float4 w = *(const float4*)(W + (size_t)(n0 + r) * NIN + k0 + c4 * 4);
            float* pb = B_s + r * PSTR + c4 * 4;
            pb[0] = w.x; pb[1] = w.y; pb[2] = w.z; pb[3] = w.w;
        }
        __syncthreads();

        const float* ab = A_s + ty * PSTR;
        const float* bb = B_s + tx * PSTR;
#pragma unroll
        for (int k = 0; k < 32; k += 4) {
            float4 a0 = *(const float4*)(ab + k);
            float4 a1 = *(const float4*)(ab + 16 * PSTR + k);
            float4 a2 = *(const float4*)(ab + 32 * PSTR + k);
            float4 a3 = *(const float4*)(ab + 48 * PSTR + k);
            float4 b0 = *(const float4*)(bb + k);
            float4 b1 = *(const float4*)(bb + 16 * PSTR + k);
            float4 b2 = *(const float4*)(bb + 32 * PSTR + k);
            float4 b3 = *(const float4*)(bb + 48 * PSTR + k);
#define PDOT(i, j, A, Bv)                                             \
            acc[i][j] += A.x * Bv.x; acc[i][j] += A.y * Bv.y;         \
            acc[i][j] += A.z * Bv.z; acc[i][j] += A.w * Bv.w
            PDOT(0,0,a0,b0); PDOT(0,1,a0,b1); PDOT(0,2,a0,b2); PDOT(0,3,a0,b3);
            PDOT(1,0,a1,b0); PDOT(1,1,a1,b1); PDOT(1,2,a1,b2); PDOT(1,3,a1,b3);
            PDOT(2,0,a2,b0); PDOT(2,1,a2,b1); PDOT(2,2,a2,b2); PDOT(2,3,a2,b3);
            PDOT(3,0,a3,b0); PDOT(3,1,a3,b1); PDOT(3,2,a3,b2); PDOT(3,3,a3,b3);
#undef PDOT
        }
    }

#pragma unroll
    for (int i = 0; i < 4; ++i) {
        int m = m0 + ty + 16 * i;
#pragma unroll
        for (int j = 0; j < 4; ++j)
            dst[(size_t)m * NDK + n0 + tx + 16 * j] = acc[i][j];
    }
}

// ---------------------------------------------------------------------------
// Kernel 2: fused attention.  One CTA = (batch b, PAIR of query tiles
// (qp, 31-qp)) so causal work is exactly 33 key-tiles per CTA:
// grid = 128 CTAs -> one balanced wave on 148 SMs.
// Per key tile: S = Q K^T / 16, clamp 10, mask (cluster>0 && j>=i),
// p = exp(s) (no running max needed: s <= 10), O += p*V, den += p.
// ---------------------------------------------------------------------------
#define QSTR 260   /* 260 mod 32 == 4 -> conflict-free float4 LDS */
#define SMEM_FLOATS (64 * QSTR * 2 + 64 * 256 + 64 * 65 + 64)
#define SMEM_BYTES  (SMEM_FLOATS * 4)

__global__ __launch_bounds__(256, 1) void attn_kernel(
    const float* __restrict__ seq,
    const float* __restrict__ cmask,
    const int*   __restrict__ causality,
    float* __restrict__ out)
{
    extern __shared__ float sm[];
    float* Q_s   = sm;                  // [64][QSTR]
    float* K_s   = Q_s + 64 * QSTR;     // [64][QSTR]
    float* V_s   = K_s + 64 * QSTR;     // [64][256]
    float* P_s   = V_s + 64 * 256;      // P_s[k*65 + q]
    float* den_s = P_s + 64 * 65;       // [64]

    const int b   = blockIdx.y;
    const int tid = threadIdx.x;
    const int ty  = tid >> 4, tx = tid & 15;
    const int causal = causality[0];

    for (int half = 0; half < 2; ++half) {
        const int qt = half ? (31 - (int)blockIdx.x) : (int)blockIdx.x;
        const int q0 = qt * 64;

        __syncthreads();  // protect smem reuse across halves

        // Load Q tile (64 x 256)
        const float* qsrc = g_q + ((size_t)b * NS + q0) * NDK;
#pragma unroll
        for (int l = 0; l < 16; ++l) {
            int idx = tid + l * 256;
            int r = idx >> 6, c4 = idx & 63;
            float4 v = *(const float4*)(qsrc + r * NDK + c4 * 4);
            float* p = Q_s + r * QSTR + c4 * 4;
            p[0] = v.x; p[1] = v.y; p[2] = v.z; p[3] = v.w;
        }
        if (tid < 64) den_s[tid] = 0.f;

        float o[4][16] = {};

        const int kt0 = causal ? qt : 0;
        for (int kt = kt0; kt < 32; ++kt) {
            const int k0 = kt * 64;
            __syncthreads();  // previous-iteration readers of K_s/V_s/P_s done

            const float* ksrc = g_k + ((size_t)b * NS + k0) * NDK;
            const float* vsrc = seq + ((size_t)b * NS + k0) * NF;
#pragma unroll
            for (int l = 0; l < 16; ++l) {
                int idx = tid + l * 256;
                int r = idx >> 6, c4 = idx & 63;
                float4 kv = *(const float4*)(ksrc + r * NDK + c4 * 4);
                float* p = K_s + r * QSTR + c4 * 4;
                p[0] = kv.x; p[1] = kv.y; p[2] = kv.z; p[3] = kv.w;
                float4 vv = *(const float4*)(vsrc + r * NF + c4 * 4);
                *(float4*)(V_s + r * 256 + c4 * 4) = vv;
            }

            // Prefetch mask tile into registers (hidden behind Phase A)
            float mreg[4][4];
            const float* mbase = cmask + (size_t)b * NS * NS + (size_t)q0 * NS + k0;
#pragma unroll
            for (int i = 0; i < 4; ++i)
#pragma unroll
                for (int j = 0; j < 4; ++j)
                    mreg[i][j] = mbase[(size_t)(ty + 16 * i) * NS + tx + 16 * j];
            __syncthreads();

            // ---- Phase A: S = Q K^T, float4 LDS, 4x4 micro-tile
            float sacc[4][4] = {};
            {
                const float* qb = Q_s + ty * QSTR;
                const float* kb = K_s + tx * QSTR;
#pragma unroll 2
                for (int d = 0; d < 256; d += 4) {
                    float4 a0 = *(const float4*)(qb + d);
                    float4 a1 = *(const float4*)(qb + 16 * QSTR + d);
                    float4 a2 = *(const float4*)(qb + 32 * QSTR + d);
                    float4 a3 = *(const float4*)(qb + 48 * QSTR + d);
                    float4 b0 = *(const float4*)(kb + d);
                    float4 b1 = *(const float4*)(kb + 16 * QSTR + d);
                    float4 b2 = *(const float4*)(kb + 32 * QSTR + d);
                    float4 b3 = *(const float4*)(kb + 48 * QSTR + d);
#define ADOT(i, j, A, Bv)                                              \
                    sacc[i][j] += A.x * Bv.x; sacc[i][j] += A.y * Bv.y;\
                    sacc[i][j] += A.z * Bv.z; sacc[i][j] += A.w * Bv.w
                    ADOT(0,0,a0,b0); ADOT(0,1,a0,b1); ADOT(0,2,a0,b2); ADOT(0,3,a0,b3);
                    ADOT(1,0,a1,b0); ADOT(1,1,a1,b1); ADOT(1,2,a1,b2); ADOT(1,3,a1,b3);
                    ADOT(2,0,a2,b0); ADOT(2,1,a2,b1); ADOT(2,2,a2,b2); ADOT(2,3,a2,b3);
                    ADOT(3,0,a3,b0); ADOT(3,1,a3,b1); ADOT(3,2,a3,b2); ADOT(3,3,a3,b3);
#undef ADOT
                }
            }

            // scale, clamp(<=10), mask, exp -> P_s[k][q]
#pragma unroll
            for (int i = 0; i < 4; ++i) {
                int q = q0 + ty + 16 * i;
#pragma unroll
                for (int j = 0; j < 4; ++j) {
                    int k = k0 + tx + 16 * j;
                    float s = fminf(sacc[i][j] * 0.0625f, 10.f);
                    bool ok = (mreg[i][j] > 0.f) && (!causal || (k >= q));
                    float p = ok ? __expf(s) : 0.f;
                    P_s[(tx + 16 * j) * 65 + ty + 16 * i] = p;
                }
            }
            __syncthreads();

            // denominator: thread q (<64) owns den_s[q]
            if (tid < 64) {
                float dsum = 0.f;
#pragma unroll 16
                for (int k = 0; k < 64; ++k) dsum += P_s[k * 65 + tid];
                den_s[tid] += dsum;
            }

            // ---- Phase B: O += P @ V (thread = 4 q-rows x 16 f-cols)
#pragma unroll 2
            for (int k = 0; k < 64; ++k) {
                float p0 = P_s[k * 65 + ty];
                float p1 = P_s[k * 65 + ty + 16];
                float p2 = P_s[k * 65 + ty + 32];
                float p3 = P_s[k * 65 + ty + 48];
#pragma unroll
                for (int r = 0; r < 4; ++r) {
                    float4 v = *(const float4*)(V_s + k * 256 + tx * 4 + 64 * r);
                    o[0][r * 4 + 0] += p0 * v.x; o[0][r * 4 + 1] += p0 * v.y;
                    o[0][r * 4 + 2] += p0 * v.z; o[0][r * 4 + 3] += p0 * v.w;
                    o[1][r * 4 + 0] += p1 * v.x; o[1][r * 4 + 1] += p1 * v.y;
                    o[1][r * 4 + 2] += p1 * v.z; o[1][r * 4 + 3] += p1 * v.w;
                    o[2][r * 4 + 0] += p2 * v.x; o[2][r * 4 + 1] += p2 * v.y;
                    o[2][r * 4 + 2] += p2 * v.z; o[2][r * 4 + 3] += p2 * v.w;
                    o[3][r * 4 + 0] += p3 * v.x; o[3][r * 4 + 1] += p3 * v.y;
                    o[3][r * 4 + 2] += p3 * v.z; o[3][r * 4 + 3] += p3 * v.w;
                }
            }
        }

        __syncthreads();  // den_s final before cross-thread read
        float* obase = out + ((size_t)b * NS + q0) * NF;
#pragma unroll
        for (int i = 0; i < 4; ++i) {
            float inv = 1.0f / den_s[ty + 16 * i];
#pragma unroll
            for (int r = 0; r < 4; ++r) {
                float4 v;
                v.x = o[i][r * 4 + 0] * inv;
                v.y = o[i][r * 4 + 1] * inv;
                v.z = o[i][r * 4 + 2] * inv;
                v.w = o[i][r * 4 + 3] * inv;
                *(float4*)(obase + (ty + 16 * i) * NF + tx * 4 + 64 * r) = v;
            }
        }
    }
}

// ---------------------------------------------------------------------------
extern "C" void kernel_launch(void* const* d_in, const int* in_sizes, int n_in,
                              void* d_out, int out_size)
{
    const float* seq  = (const float*)d_in[0];
    const float* pos  = (const float*)d_in[1];
    const float* tim  = (const float*)d_in[2];
    const float* Wq   = (const float*)d_in[3];
    const float* Wk   = (const float*)d_in[4];
    const float* cm   = (const float*)d_in[5];
    const int*   caus = (const int*)d_in[6];
    float* out = (float*)d_out;

    cudaFuncSetAttribute(attn_kernel,
                         cudaFuncAttributeMaxDynamicSharedMemorySize, SMEM_BYTES);

    dim3 gp(NB * NS / 64, NDK / 64, 2);  // (256, 4, 2)
    proj_kernel<<<gp, 256>>>(seq, pos, tim, Wq, Wk);

    dim3 ga(16, NB);                     // 128 CTAs, 33 key-tiles each (causal)
    attn_kernel<<<ga, 256, SMEM_BYTES>>>(seq, cm, caus, out);
}

// round 4
// speedup vs baseline: 2.4806x; 1.0141x over previous
#include <cuda_runtime.h>

#define NB 8
#define NS 2048
#define NF 256
#define NE 64
#define NDK 256
#define NIN 384

typedef unsigned long long ull;

// Packed fp32x2 FMA (Blackwell FFMA2): acc = a*b + acc, two fp32 lanes per issue.
#define FFMA2(acc, a, b) \
    asm("fma.rn.f32x2 %0, %1, %2, %0;" : "+l"(acc) : "l"(a), "l"(b))
#define BCAST2(d, s) \
    asm("mov.b64 %0, {%1, %1};" : "=l"(d) : "f"(s))
#define UNPACK2(lo, hi, s) \
    asm("mov.b64 {%0, %1}, %2;" : "=f"(lo), "=f"(hi) : "l"(s))

// Scratch for projected Q and K — __device__ globals (no allocs).
__device__ float g_q[(size_t)NB * NS * NDK];
__device__ float g_k[(size_t)NB * NS * NDK];

// ---------------------------------------------------------------------------
// Kernel 1: Q/K projection.  C[16384,256] = concat(seq,pos,time) @ W^T
// 64x64 tile, BK=32, 4x4 micro-tile, FFMA2 inner product.
// PSTR=36 floats (144B, 16B-aligned rows; 36 mod 32 = 4 -> conflict-free).
// ---------------------------------------------------------------------------
#define PSTR 36

__global__ __launch_bounds__(256) void proj_kernel(
    const float* __restrict__ seq,
    const float* __restrict__ pos,
    const float* __restrict__ tim,
    const float* __restrict__ Wq,
    const float* __restrict__ Wk)
{
    __shared__ float A_s[64 * PSTR];
    __shared__ float B_s[64 * PSTR];

    const float* W   = blockIdx.z ? Wk : Wq;
    float*       dst = blockIdx.z ? g_k : g_q;
    const int m0 = blockIdx.x * 64;
    const int n0 = blockIdx.y * 64;
    const int tid = threadIdx.x;
    const int ty = tid >> 4, tx = tid & 15;

    ull acc2[4][4];
#pragma unroll
    for (int i = 0; i < 4; ++i)
#pragma unroll
        for (int j = 0; j < 4; ++j) acc2[i][j] = 0ull;

    for (int kt = 0; kt < 12; ++kt) {
        const float* src; int width, colbase;
        if (kt < 8)       { src = seq; width = NF; colbase = kt * 32; }
        else if (kt < 10) { src = pos; width = NE; colbase = (kt - 8) * 32; }
        else              { src = tim; width = NE; colbase = (kt - 10) * 32; }
        const int k0 = kt * 32;

        __syncthreads();
#pragma unroll
        for (int l = 0; l < 2; ++l) {
            int idx = tid + l * 256;
            int r = idx >> 3, c4 = idx & 7;
            float4 a = *(const float4*)(src + (size_t)(m0 + r) * width + colbase + c4 * 4);
            float* pa = A_s + r * PSTR + c4 * 4;
            pa[0] = a.x; pa[1] = a.y; pa[2] = a.z; pa[3] = a.w;
            float4 w = *(const float4*)(W + (size_t)(n0 + r) * NIN + k0 + c4 * 4);
            float* pb = B_s + r * PSTR + c4 * 4;
            pb[0] = w.x; pb[1] = w.y; pb[2] = w.z; pb[3] = w.w;
        }
        __syncthreads();

        const float* ab = A_s + ty * PSTR;
        const float* bb = B_s + tx * PSTR;
#pragma unroll
        for (int k = 0; k < 32; k += 4) {
            ulonglong2 a0 = *(const ulonglong2*)(ab + k);
            ulonglong2 a1 = *(const ulonglong2*)(ab + 16 * PSTR + k);
            ulonglong2 a2 = *(const ulonglong2*)(ab + 32 * PSTR + k);
            ulonglong2 a3 = *(const ulonglong2*)(ab + 48 * PSTR + k);
            ulonglong2 b0 = *(const ulonglong2*)(bb + k);
            ulonglong2 b1 = *(const ulonglong2*)(bb + 16 * PSTR + k);
            ulonglong2 b2 = *(const ulonglong2*)(bb + 32 * PSTR + k);
            ulonglong2 b3 = *(const ulonglong2*)(bb + 48 * PSTR + k);
#define PDOT(i, j, A, Bv) \
            FFMA2(acc2[i][j], A.x, Bv.x); FFMA2(acc2[i][j], A.y, Bv.y)
            PDOT(0,0,a0,b0); PDOT(0,1,a0,b1); PDOT(0,2,a0,b2); PDOT(0,3,a0,b3);
            PDOT(1,0,a1,b0); PDOT(1,1,a1,b1); PDOT(1,2,a1,b2); PDOT(1,3,a1,b3);
            PDOT(2,0,a2,b0); PDOT(2,1,a2,b1); PDOT(2,2,a2,b2); PDOT(2,3,a2,b3);
            PDOT(3,0,a3,b0); PDOT(3,1,a3,b1); PDOT(3,2,a3,b2); PDOT(3,3,a3,b3);
#undef PDOT
        }
    }

#pragma unroll
    for (int i = 0; i < 4; ++i) {
        int m = m0 + ty + 16 * i;
#pragma unroll
        for (int j = 0; j < 4; ++j) {
            float lo, hi; UNPACK2(lo, hi, acc2[i][j]);
            dst[(size_t)m * NDK + n0 + tx + 16 * j] = lo + hi;
        }
    }
}

// ---------------------------------------------------------------------------
// Kernel 2: fused attention.  One CTA = (batch b, PAIR of query tiles
// (qp, 31-qp)) -> exactly 33 causal key-tiles per CTA, 128 CTAs = 1 wave.
// Per key tile: S = Q K^T / 16, clamp 10, mask (cluster>0 && j>=i),
// p = exp(s) (s <= 10, no running max needed), O += p*V, den += p.
// Both GEMM phases use packed FFMA2.
// ---------------------------------------------------------------------------
#define QSTR 260   /* 260*4=1040B rows: 16B-aligned, 260 mod 32 == 4 */
#define SMEM_FLOATS (64 * QSTR * 2 + 64 * 256 + 64 * 65 + 64)
#define SMEM_BYTES  (SMEM_FLOATS * 4)

__global__ __launch_bounds__(256, 1) void attn_kernel(
    const float* __restrict__ seq,
    const float* __restrict__ cmask,
    const int*   __restrict__ causality,
    float* __restrict__ out)
{
    extern __shared__ float sm[];
    float* Q_s   = sm;                  // [64][QSTR]
    float* K_s   = Q_s + 64 * QSTR;     // [64][QSTR]
    float* V_s   = K_s + 64 * QSTR;     // [64][256]
    float* P_s   = V_s + 64 * 256;      // P_s[k*65 + q]
    float* den_s = P_s + 64 * 65;       // [64]

    const int b   = blockIdx.y;
    const int tid = threadIdx.x;
    const int ty  = tid >> 4, tx = tid & 15;
    const int causal = causality[0];

    for (int half = 0; half < 2; ++half) {
        const int qt = half ? (31 - (int)blockIdx.x) : (int)blockIdx.x;
        const int q0 = qt * 64;

        __syncthreads();  // protect smem reuse across halves

        // Load Q tile (64 x 256)
        const float* qsrc = g_q + ((size_t)b * NS + q0) * NDK;
#pragma unroll
        for (int l = 0; l < 16; ++l) {
            int idx = tid + l * 256;
            int r = idx >> 6, c4 = idx & 63;
            float4 v = *(const float4*)(qsrc + r * NDK + c4 * 4);
            float* p = Q_s + r * QSTR + c4 * 4;
            p[0] = v.x; p[1] = v.y; p[2] = v.z; p[3] = v.w;
        }
        if (tid < 64) den_s[tid] = 0.f;

        ull o2[4][8];
#pragma unroll
        for (int i = 0; i < 4; ++i)
#pragma unroll
            for (int c = 0; c < 8; ++c) o2[i][c] = 0ull;

        const int kt0 = causal ? qt : 0;
        for (int kt = kt0; kt < 32; ++kt) {
            const int k0 = kt * 64;
            __syncthreads();  // previous-iteration readers of K_s/V_s/P_s done

            const float* ksrc = g_k + ((size_t)b * NS + k0) * NDK;
            const float* vsrc = seq + ((size_t)b * NS + k0) * NF;
#pragma unroll
            for (int l = 0; l < 16; ++l) {
                int idx = tid + l * 256;
                int r = idx >> 6, c4 = idx & 63;
                float4 kv = *(const float4*)(ksrc + r * NDK + c4 * 4);
                float* p = K_s + r * QSTR + c4 * 4;
                p[0] = kv.x; p[1] = kv.y; p[2] = kv.z; p[3] = kv.w;
                float4 vv = *(const float4*)(vsrc + r * NF + c4 * 4);
                *(float4*)(V_s + r * 256 + c4 * 4) = vv;
            }

            // Prefetch mask tile into registers (hidden behind Phase A)
            float mreg[4][4];
            const float* mbase = cmask + (size_t)b * NS * NS + (size_t)q0 * NS + k0;
#pragma unroll
            for (int i = 0; i < 4; ++i)
#pragma unroll
                for (int j = 0; j < 4; ++j)
                    mreg[i][j] = mbase[(size_t)(ty + 16 * i) * NS + tx + 16 * j];
            __syncthreads();

            // ---- Phase A: S = Q K^T, packed FFMA2, 4x4 micro-tile
            ull sacc2[4][4];
#pragma unroll
            for (int i = 0; i < 4; ++i)
#pragma unroll
                for (int j = 0; j < 4; ++j) sacc2[i][j] = 0ull;
            {
                const float* qb = Q_s + ty * QSTR;
                const float* kb = K_s + tx * QSTR;
#pragma unroll 2
                for (int d = 0; d < 256; d += 4) {
                    ulonglong2 a0 = *(const ulonglong2*)(qb + d);
                    ulonglong2 a1 = *(const ulonglong2*)(qb + 16 * QSTR + d);
                    ulonglong2 a2 = *(const ulonglong2*)(qb + 32 * QSTR + d);
                    ulonglong2 a3 = *(const ulonglong2*)(qb + 48 * QSTR + d);
                    ulonglong2 b0 = *(const ulonglong2*)(kb + d);
                    ulonglong2 b1 = *(const ulonglong2*)(kb + 16 * QSTR + d);
                    ulonglong2 b2 = *(const ulonglong2*)(kb + 32 * QSTR + d);
                    ulonglong2 b3 = *(const ulonglong2*)(kb + 48 * QSTR + d);
#define ADOT(i, j, A, Bv) \
                    FFMA2(sacc2[i][j], A.x, Bv.x); FFMA2(sacc2[i][j], A.y, Bv.y)
                    ADOT(0,0,a0,b0); ADOT(0,1,a0,b1); ADOT(0,2,a0,b2); ADOT(0,3,a0,b3);
                    ADOT(1,0,a1,b0); ADOT(1,1,a1,b1); ADOT(1,2,a1,b2); ADOT(1,3,a1,b3);
                    ADOT(2,0,a2,b0); ADOT(2,1,a2,b1); ADOT(2,2,a2,b2); ADOT(2,3,a2,b3);
                    ADOT(3,0,a3,b0); ADOT(3,1,a3,b1); ADOT(3,2,a3,b2); ADOT(3,3,a3,b3);
#undef ADOT
                }
            }

            // scale, clamp(<=10), mask, exp -> P_s[k][q]
#pragma unroll
            for (int i = 0; i < 4; ++i) {
                int q = q0 + ty + 16 * i;
#pragma unroll
                for (int j = 0; j < 4; ++j) {
                    int k = k0 + tx + 16 * j;
                    float lo, hi; UNPACK2(lo, hi, sacc2[i][j]);
                    float s = fminf((lo + hi) * 0.0625f, 10.f);
                    bool ok = (mreg[i][j] > 0.f) && (!causal || (k >= q));
                    float p = ok ? __expf(s) : 0.f;
                    P_s[(tx + 16 * j) * 65 + ty + 16 * i] = p;
                }
            }
            __syncthreads();

            // denominator: thread q (<64) owns den_s[q]
            if (tid < 64) {
                float dsum = 0.f;
#pragma unroll 16
                for (int k = 0; k < 64; ++k) dsum += P_s[k * 65 + tid];
                den_s[tid] += dsum;
            }

            // ---- Phase B: O += P @ V, packed FFMA2
#pragma unroll 2
            for (int k = 0; k < 64; ++k) {
                float p0 = P_s[k * 65 + ty];
                float p1 = P_s[k * 65 + ty + 16];
                float p2 = P_s[k * 65 + ty + 32];
                float p3 = P_s[k * 65 + ty + 48];
                ull pp0, pp1, pp2, pp3;
                BCAST2(pp0, p0); BCAST2(pp1, p1);
                BCAST2(pp2, p2); BCAST2(pp3, p3);
#pragma unroll
                for (int r = 0; r < 4; ++r) {
                    ulonglong2 v = *(const ulonglong2*)(V_s + k * 256 + tx * 4 + 64 * r);
                    FFMA2(o2[0][r * 2 + 0], pp0, v.x); FFMA2(o2[0][r * 2 + 1], pp0, v.y);
                    FFMA2(o2[1][r * 2 + 0], pp1, v.x); FFMA2(o2[1][r * 2 + 1], pp1, v.y);
                    FFMA2(o2[2][r * 2 + 0], pp2, v.x); FFMA2(o2[2][r * 2 + 1], pp2, v.y);
                    FFMA2(o2[3][r * 2 + 0], pp3, v.x); FFMA2(o2[3][r * 2 + 1], pp3, v.y);
                }
            }
        }

        __syncthreads();  // den_s final before cross-thread read
        float* obase = out + ((size_t)b * NS + q0) * NF;
#pragma unroll
        for (int i = 0; i < 4; ++i) {
            float inv = 1.0f / den_s[ty + 16 * i];
#pragma unroll
            for (int r = 0; r < 4; ++r) {
                float x0, x1, x2, x3;
                UNPACK2(x0, x1, o2[i][r * 2 + 0]);
                UNPACK2(x2, x3, o2[i][r * 2 + 1]);
                float4 v;
                v.x = x0 * inv; v.y = x1 * inv; v.z = x2 * inv; v.w = x3 * inv;
                *(float4*)(obase + (ty + 16 * i) * NF + tx * 4 + 64 * r) = v;
            }
        }
    }
}

// ---------------------------------------------------------------------------
extern "C" void kernel_launch(void* const* d_in, const int* in_sizes, int n_in,
                              void* d_out, int out_size)
{
    const float* seq  = (const float*)d_in[0];
    const float* pos  = (const float*)d_in[1];
    const float* tim  = (const float*)d_in[2];
    const float* Wq   = (const float*)d_in[3];
    const float* Wk   = (const float*)d_in[4];
    const float* cm   = (const float*)d_in[5];
    const int*   caus = (const int*)d_in[6];
    float* out = (float*)d_out;

    cudaFuncSetAttribute(attn_kernel,
                         cudaFuncAttributeMaxDynamicSharedMemorySize, SMEM_BYTES);

    dim3 gp(NB * NS / 64, NDK / 64, 2);  // (256, 4, 2)
    proj_kernel<<<gp, 256>>>(seq, pos, tim, Wq, Wk);

    dim3 ga(16, NB);                     // 128 CTAs, 33 key-tiles each (causal)
    attn_kernel<<<ga, 256, SMEM_BYTES>>>(seq, cm, caus, out);
}

// round 5
// speedup vs baseline: 2.4825x; 1.0008x over previous
#include <cuda_runtime.h>

#define NB 8
#define NS 2048
#define NF 256
#define NE 64
#define NDK 256
#define NIN 384

typedef unsigned long long ull;

// Packed fp32x2 FMA (Blackwell FFMA2): acc = a*b + acc, two fp32 lanes per issue.
#define FFMA2(acc, a, b) \
    asm("fma.rn.f32x2 %0, %1, %2, %0;" : "+l"(acc) : "l"(a), "l"(b))
#define BCAST2(d, s) \
    asm("mov.b64 %0, {%1, %1};" : "=l"(d) : "f"(s))
#define UNPACK2(lo, hi, s) \
    asm("mov.b64 {%0, %1}, %2;" : "=f"(lo), "=f"(hi) : "l"(s))

// Scratch for projected Q and K — __device__ globals (no allocs).
__device__ float g_q[(size_t)NB * NS * NDK];
__device__ float g_k[(size_t)NB * NS * NDK];

// ---------------------------------------------------------------------------
// Kernel 1: Q/K projection.  C[16384,256] = concat(seq,pos,time) @ W^T
// 64x64 tile, BK=32, 4x4 micro-tile, FFMA2 inner product.
// PSTR=36 floats (144B, 16B-aligned rows; 36 mod 32 = 4 -> conflict-free).
// ---------------------------------------------------------------------------
#define PSTR 36

__global__ __launch_bounds__(256) void proj_kernel(
    const float* __restrict__ seq,
    const float* __restrict__ pos,
    const float* __restrict__ tim,
    const float* __restrict__ Wq,
    const float* __restrict__ Wk)
{
    __shared__ float A_s[64 * PSTR];
    __shared__ float B_s[64 * PSTR];

    const float* W   = blockIdx.z ? Wk : Wq;
    float*       dst = blockIdx.z ? g_k : g_q;
    const int m0 = blockIdx.x * 64;
    const int n0 = blockIdx.y * 64;
    const int tid = threadIdx.x;
    const int ty = tid >> 4, tx = tid & 15;

    ull acc2[4][4];
#pragma unroll
    for (int i = 0; i < 4; ++i)
#pragma unroll
        for (int j = 0; j < 4; ++j) acc2[i][j] = 0ull;

    for (int kt = 0; kt < 12; ++kt) {
        const float* src; int width, colbase;
        if (kt < 8)       { src = seq; width = NF; colbase = kt * 32; }
        else if (kt < 10) { src = pos; width = NE; colbase = (kt - 8) * 32; }
        else              { src = tim; width = NE; colbase = (kt - 10) * 32; }
        const int k0 = kt * 32;

        __syncthreads();
#pragma unroll
        for (int l = 0; l < 2; ++l) {
            int idx = tid + l * 256;
            int r = idx >> 3, c4 = idx & 7;
            float4 a = *(const float4*)(src + (size_t)(m0 + r) * width + colbase + c4 * 4);
            float* pa = A_s + r * PSTR + c4 * 4;
            pa[0] = a.x; pa[1] = a.y; pa[2] = a.z; pa[3] = a.w;
            float4 w = *(const float4*)(W + (size_t)(n0 + r) * NIN + k0 + c4 * 4);
            float* pb = B_s + r * PSTR + c4 * 4;
            pb[0] = w.x; pb[1] = w.y; pb[2] = w.z; pb[3] = w.w;
        }
        __syncthreads();

        const float* ab = A_s + ty * PSTR;
        const float* bb = B_s + tx * PSTR;
#pragma unroll
        for (int k = 0; k < 32; k += 4) {
            ulonglong2 a0 = *(const ulonglong2*)(ab + k);
            ulonglong2 a1 = *(const ulonglong2*)(ab + 16 * PSTR + k);
            ulonglong2 a2 = *(const ulonglong2*)(ab + 32 * PSTR + k);
            ulonglong2 a3 = *(const ulonglong2*)(ab + 48 * PSTR + k);
            ulonglong2 b0 = *(const ulonglong2*)(bb + k);
            ulonglong2 b1 = *(const ulonglong2*)(bb + 16 * PSTR + k);
            ulonglong2 b2 = *(const ulonglong2*)(bb + 32 * PSTR + k);
            ulonglong2 b3 = *(const ulonglong2*)(bb + 48 * PSTR + k);
#define PDOT(i, j, A, Bv) \
            FFMA2(acc2[i][j], A.x, Bv.x); FFMA2(acc2[i][j], A.y, Bv.y)
            PDOT(0,0,a0,b0); PDOT(0,1,a0,b1); PDOT(0,2,a0,b2); PDOT(0,3,a0,b3);
            PDOT(1,0,a1,b0); PDOT(1,1,a1,b1); PDOT(1,2,a1,b2); PDOT(1,3,a1,b3);
            PDOT(2,0,a2,b0); PDOT(2,1,a2,b1); PDOT(2,2,a2,b2); PDOT(2,3,a2,b3);
            PDOT(3,0,a3,b0); PDOT(3,1,a3,b1); PDOT(3,2,a3,b2); PDOT(3,3,a3,b3);
#undef PDOT
        }
    }

#pragma unroll
    for (int i = 0; i < 4; ++i) {
        int m = m0 + ty + 16 * i;
#pragma unroll
        for (int j = 0; j < 4; ++j) {
            float lo, hi; UNPACK2(lo, hi, acc2[i][j]);
            dst[(size_t)m * NDK + n0 + tx + 16 * j] = lo + hi;
        }
    }
}

// ---------------------------------------------------------------------------
// Kernel 2: fused attention.  One CTA = (batch b, PAIR of query tiles
// (qp, 31-qp)) -> exactly 33 causal key-tiles per CTA, 128 CTAs = 1 wave.
// Per key tile: S = Q K^T / 16, clamp 10, mask (cluster>0 && j>=i),
// p = exp(s) (s <= 10, no running max needed), O += p*V, den += p.
// Both GEMM phases use packed FFMA2.
// ---------------------------------------------------------------------------
#define QSTR 260   /* 260*4=1040B rows: 16B-aligned, 260 mod 32 == 4 */
#define SMEM_FLOATS (64 * QSTR * 2 + 64 * 256 + 64 * 65 + 64)
#define SMEM_BYTES  (SMEM_FLOATS * 4)

__global__ __launch_bounds__(256, 1) void attn_kernel(
    const float* __restrict__ seq,
    const float* __restrict__ cmask,
    const int*   __restrict__ causality,
    float* __restrict__ out)
{
    extern __shared__ float sm[];
    float* Q_s   = sm;                  // [64][QSTR]
    float* K_s   = Q_s + 64 * QSTR;     // [64][QSTR]
    float* V_s   = K_s + 64 * QSTR;     // [64][256]
    float* P_s   = V_s + 64 * 256;      // P_s[k*65 + q]
    float* den_s = P_s + 64 * 65;       // [64]

    const int b   = blockIdx.y;
    const int tid = threadIdx.x;
    const int ty  = tid >> 4, tx = tid & 15;
    const int causal = causality[0];

    for (int half = 0; half < 2; ++half) {
        const int qt = half ? (31 - (int)blockIdx.x) : (int)blockIdx.x;
        const int q0 = qt * 64;

        __syncthreads();  // protect smem reuse across halves

        // Load Q tile (64 x 256)
        const float* qsrc = g_q + ((size_t)b * NS + q0) * NDK;
#pragma unroll
        for (int l = 0; l < 16; ++l) {
            int idx = tid + l * 256;
            int r = idx >> 6, c4 = idx & 63;
            float4 v = *(const float4*)(qsrc + r * NDK + c4 * 4);
            float* p = Q_s + r * QSTR + c4 * 4;
            p[0] = v.x; p[1] = v.y; p[2] = v.z; p[3] = v.w;
        }
        if (tid < 64) den_s[tid] = 0.f;

        ull o2[4][8];
#pragma unroll
        for (int i = 0; i < 4; ++i)
#pragma unroll
            for (int c = 0; c < 8; ++c) o2[i][c] = 0ull;

        const int kt0 = causal ? qt : 0;
        for (int kt = kt0; kt < 32; ++kt) {
            const int k0 = kt * 64;
            __syncthreads();  // previous-iteration readers of K_s/V_s/P_s done

            const float* ksrc = g_k + ((size_t)b * NS + k0) * NDK;
            const float* vsrc = seq + ((size_t)b * NS + k0) * NF;
#pragma unroll
            for (int l = 0; l < 16; ++l) {
                int idx = tid + l * 256;
                int r = idx >> 6, c4 = idx & 63;
                float4 kv = *(const float4*)(ksrc + r * NDK + c4 * 4);
                float* p = K_s + r * QSTR + c4 * 4;
                p[0] = kv.x; p[1] = kv.y; p[2] = kv.z; p[3] = kv.w;
                float4 vv = *(const float4*)(vsrc + r * NF + c4 * 4);
                *(float4*)(V_s + r * 256 + c4 * 4) = vv;
            }

            // Prefetch mask tile into registers (hidden behind Phase A)
            float mreg[4][4];
            const float* mbase = cmask + (size_t)b * NS * NS + (size_t)q0 * NS + k0;
#pragma unroll
            for (int i = 0; i < 4; ++i)
#pragma unroll
                for (int j = 0; j < 4; ++j)
                    mreg[i][j] = mbase[(size_t)(ty + 16 * i) * NS + tx + 16 * j];
            __syncthreads();

            // ---- Phase A: S = Q K^T, packed FFMA2, 4x4 micro-tile
            ull sacc2[4][4];
#pragma unroll
            for (int i = 0; i < 4; ++i)
#pragma unroll
                for (int j = 0; j < 4; ++j) sacc2[i][j] = 0ull;
            {
                const float* qb = Q_s + ty * QSTR;
                const float* kb = K_s + tx * QSTR;
#pragma unroll 2
                for (int d = 0; d < 256; d += 4) {
                    ulonglong2 a0 = *(const ulonglong2*)(qb + d);
                    ulonglong2 a1 = *(const ulonglong2*)(qb + 16 * QSTR + d);
                    ulonglong2 a2 = *(const ulonglong2*)(qb + 32 * QSTR + d);
                    ulonglong2 a3 = *(const ulonglong2*)(qb + 48 * QSTR + d);
                    ulonglong2 b0 = *(const ulonglong2*)(kb + d);
                    ulonglong2 b1 = *(const ulonglong2*)(kb + 16 * QSTR + d);
                    ulonglong2 b2 = *(const ulonglong2*)(kb + 32 * QSTR + d);
                    ulonglong2 b3 = *(const ulonglong2*)(kb + 48 * QSTR + d);
#define ADOT(i, j, A, Bv) \
                    FFMA2(sacc2[i][j], A.x, Bv.x); FFMA2(sacc2[i][j], A.y, Bv.y)
                    ADOT(0,0,a0,b0); ADOT(0,1,a0,b1); ADOT(0,2,a0,b2); ADOT(0,3,a0,b3);
                    ADOT(1,0,a1,b0); ADOT(1,1,a1,b1); ADOT(1,2,a1,b2); ADOT(1,3,a1,b3);
                    ADOT(2,0,a2,b0); ADOT(2,1,a2,b1); ADOT(2,2,a2,b2); ADOT(2,3,a2,b3);
                    ADOT(3,0,a3,b0); ADOT(3,1,a3,b1); ADOT(3,2,a3,b2); ADOT(3,3,a3,b3);
#undef ADOT
                }
            }

            // scale, clamp(<=10), mask, exp -> P_s[k][q]
#pragma unroll
            for (int i = 0; i < 4; ++i) {
                int q = q0 + ty + 16 * i;
#pragma unroll
                for (int j = 0; j < 4; ++j) {
                    int k = k0 + tx + 16 * j;
                    float lo, hi; UNPACK2(lo, hi, sacc2[i][j]);
                    float s = fminf((lo + hi) * 0.0625f, 10.f);
                    bool ok = (mreg[i][j] > 0.f) && (!causal || (k >= q));
                    float p = ok ? __expf(s) : 0.f;
                    P_s[(tx + 16 * j) * 65 + ty + 16 * i] = p;
                }
            }
            __syncthreads();

            // denominator: thread q (<64) owns den_s[q]
            if (tid < 64) {
                float dsum = 0.f;
#pragma unroll 16
                for (int k = 0; k < 64; ++k) dsum += P_s[k * 65 + tid];
                den_s[tid] += dsum;
            }

            // ---- Phase B: O += P @ V, packed FFMA2
#pragma unroll 2
            for (int k = 0; k < 64; ++k) {
                float p0 = P_s[k * 65 + ty];
                float p1 = P_s[k * 65 + ty + 16];
                float p2 = P_s[k * 65 + ty + 32];
                float p3 = P_s[k * 65 + ty + 48];
                ull pp0, pp1, pp2, pp3;
                BCAST2(pp0, p0); BCAST2(pp1, p1);
                BCAST2(pp2, p2); BCAST2(pp3, p3);
#pragma unroll
                for (int r = 0; r < 4; ++r) {
                    ulonglong2 v = *(const ulonglong2*)(V_s + k * 256 + tx * 4 + 64 * r);
                    FFMA2(o2[0][r * 2 + 0], pp0, v.x); FFMA2(o2[0][r * 2 + 1], pp0, v.y);
                    FFMA2(o2[1][r * 2 + 0], pp1, v.x); FFMA2(o2[1][r * 2 + 1], pp1, v.y);
                    FFMA2(o2[2][r * 2 + 0], pp2, v.x); FFMA2(o2[2][r * 2 + 1], pp2, v.y);
                    FFMA2(o2[3][r * 2 + 0], pp3, v.x); FFMA2(o2[3][r * 2 + 1], pp3, v.y);
                }
            }
        }

        __syncthreads();  // den_s final before cross-thread read
        float* obase = out + ((size_t)b * NS + q0) * NF;
#pragma unroll
        for (int i = 0; i < 4; ++i) {
            float inv = 1.0f / den_s[ty + 16 * i];
#pragma unroll
            for (int r = 0; r < 4; ++r) {
                float x0, x1, x2, x3;
                UNPACK2(x0, x1, o2[i][r * 2 + 0]);
                UNPACK2(x2, x3, o2[i][r * 2 + 1]);
                float4 v;
                v.x = x0 * inv; v.y = x1 * inv; v.z = x2 * inv; v.w = x3 * inv;
                *(float4*)(obase + (ty + 16 * i) * NF + tx * 4 + 64 * r) = v;
            }
        }
    }
}

// ---------------------------------------------------------------------------
extern "C" void kernel_launch(void* const* d_in, const int* in_sizes, int n_in,
                              void* d_out, int out_size)
{
    const float* seq  = (const float*)d_in[0];
    const float* pos  = (const float*)d_in[1];
    const float* tim  = (const float*)d_in[2];
    const float* Wq   = (const float*)d_in[3];
    const float* Wk   = (const float*)d_in[4];
    const float* cm   = (const float*)d_in[5];
    const int*   caus = (const int*)d_in[6];
    float* out = (float*)d_out;

    cudaFuncSetAttribute(attn_kernel,
                         cudaFuncAttributeMaxDynamicSharedMemorySize, SMEM_BYTES);

    dim3 gp(NB * NS / 64, NDK / 64, 2);  // (256, 4, 2)
    proj_kernel<<<gp, 256>>>(seq, pos, tim, Wq, Wk);

    dim3 ga(16, NB);                     // 128 CTAs, 33 key-tiles each (causal)
    attn_kernel<<<ga, 256, SMEM_BYTES>>>(seq, cm, caus, out);
}

// round 9
// speedup vs baseline: 4.0934x; 1.6489x over previous
#include <cuda_runtime.h>
#include <cuda_bf16.h>
#include <cstdint>

#define NB 8
#define NS 2048
#define NF 256
#define NE 64
#define NDK 256
#define NIN 384

typedef unsigned long long ull;

// Packed fp32x2 FMA (proj kernel)
#define FFMA2(acc, a, b) \
    asm("fma.rn.f32x2 %0, %1, %2, %0;" : "+l"(acc) : "l"(a), "l"(b))
#define UNPACK2(lo, hi, s) \
    asm("mov.b64 {%0, %1}, %2;" : "=f"(lo), "=f"(hi) : "l"(s))

__device__ __forceinline__ void mma_bf16(float d[4], const uint32_t a[4],
                                         uint32_t b0, uint32_t b1) {
    asm volatile(
        "mma.sync.aligned.m16n8k16.row.col.f32.bf16.bf16.f32 "
        "{%0,%1,%2,%3}, {%4,%5,%6,%7}, {%8,%9}, {%0,%1,%2,%3};"
        : "+f"(d[0]), "+f"(d[1]), "+f"(d[2]), "+f"(d[3])
        : "r"(a[0]), "r"(a[1]), "r"(a[2]), "r"(a[3]), "r"(b0), "r"(b1));
}

// ---------------------------------------------------------------------------
// Global scratch (bf16 hi/lo splits)
// ---------------------------------------------------------------------------
__device__ __nv_bfloat16 g_qh[(size_t)NB * NS * NDK];
__device__ __nv_bfloat16 g_ql[(size_t)NB * NS * NDK];
__device__ __nv_bfloat16 g_kh[(size_t)NB * NS * NDK];
__device__ __nv_bfloat16 g_kl[(size_t)NB * NS * NDK];
__device__ __nv_bfloat16 g_vth[(size_t)NB * NF * NS];  // [b][f][s]
__device__ __nv_bfloat16 g_vtl[(size_t)NB * NF * NS];

// ---------------------------------------------------------------------------
// Kernel 1: Q/K projection (FFMA2 fp32) -> bf16 hi/lo outputs
// ---------------------------------------------------------------------------
#define PSTR 36
__global__ __launch_bounds__(256) void proj_kernel(
    const float* __restrict__ seq, const float* __restrict__ pos,
    const float* __restrict__ tim, const float* __restrict__ Wq,
    const float* __restrict__ Wk)
{
    __shared__ float A_s[64 * PSTR];
    __shared__ float B_s[64 * PSTR];

    const float* W = blockIdx.z ? Wk : Wq;
    __nv_bfloat16* dh = blockIdx.z ? g_kh : g_qh;
    __nv_bfloat16* dl = blockIdx.z ? g_kl : g_ql;
    const int m0 = blockIdx.x * 64, n0 = blockIdx.y * 64;
    const int tid = threadIdx.x, ty = tid >> 4, tx = tid & 15;

    ull acc2[4][4];
#pragma unroll
    for (int i = 0; i < 4; ++i)
#pragma unroll
        for (int j = 0; j < 4; ++j) acc2[i][j] = 0ull;

    for (int kt = 0; kt < 12; ++kt) {
        const float* src; int width, colbase;
        if (kt < 8)       { src = seq; width = NF; colbase = kt * 32; }
        else if (kt < 10) { src = pos; width = NE; colbase = (kt - 8) * 32; }
        else              { src = tim; width = NE; colbase = (kt - 10) * 32; }
        const int k0 = kt * 32;

        __syncthreads();
#pragma unroll
        for (int l = 0; l < 2; ++l) {
            int idx = tid + l * 256, r = idx >> 3, c4 = idx & 7;
            float4 a = *(const float4*)(src + (size_t)(m0 + r) * width + colbase + c4 * 4);
            float* pa = A_s + r * PSTR + c4 * 4;
            pa[0] = a.x; pa[1] = a.y; pa[2] = a.z; pa[3] = a.w;
            float4 w = *(const float4*)(W + (size_t)(n0 + r) * NIN + k0 + c4 * 4);
            float* pb = B_s + r * PSTR + c4 * 4;
            pb[0] = w.x; pb[1] = w.y; pb[2] = w.z; pb[3] = w.w;
        }
        __syncthreads();

        const float* ab = A_s + ty * PSTR;
        const float* bb = B_s + tx * PSTR;
#pragma unroll
        for (int k = 0; k < 32; k += 4) {
            ulonglong2 a0 = *(const ulonglong2*)(ab + k);
            ulonglong2 a1 = *(const ulonglong2*)(ab + 16 * PSTR + k);
            ulonglong2 a2 = *(const ulonglong2*)(ab + 32 * PSTR + k);
            ulonglong2 a3 = *(const ulonglong2*)(ab + 48 * PSTR + k);
            ulonglong2 b0 = *(const ulonglong2*)(bb + k);
            ulonglong2 b1 = *(const ulonglong2*)(bb + 16 * PSTR + k);
            ulonglong2 b2 = *(const ulonglong2*)(bb + 32 * PSTR + k);
            ulonglong2 b3 = *(const ulonglong2*)(bb + 48 * PSTR + k);
#define PDOT(i, j, A, Bv) \
            FFMA2(acc2[i][j], A.x, Bv.x); FFMA2(acc2[i][j], A.y, Bv.y)
            PDOT(0,0,a0,b0); PDOT(0,1,a0,b1); PDOT(0,2,a0,b2); PDOT(0,3,a0,b3);
            PDOT(1,0,a1,b0); PDOT(1,1,a1,b1); PDOT(1,2,a1,b2); PDOT(1,3,a1,b3);
            PDOT(2,0,a2,b0); PDOT(2,1,a2,b1); PDOT(2,2,a2,b2); PDOT(2,3,a2,b3);
            PDOT(3,0,a3,b0); PDOT(3,1,a3,b1); PDOT(3,2,a3,b2); PDOT(3,3,a3,b3);
#undef PDOT
        }
    }

#pragma unroll
    for (int i = 0; i < 4; ++i) {
        int m = m0 + ty + 16 * i;
#pragma unroll
        for (int j = 0; j < 4; ++j) {
            float lo, hi; UNPACK2(lo, hi, acc2[i][j]);
            float c = lo + hi;
            __nv_bfloat16 h = __float2bfloat16_rn(c);
            float l = c - __bfloat162float(h);
            size_t idx = (size_t)m * NDK + n0 + tx + 16 * j;
            dh[idx] = h;
            dl[idx] = __float2bfloat16_rn(l);
        }
    }
}

// ---------------------------------------------------------------------------
// Kernel 2: V = seq transpose + bf16 split: g_vt{h,l}[b][f][s]
// ---------------------------------------------------------------------------
__global__ __launch_bounds__(256) void vsplit_kernel(const float* __restrict__ seq)
{
    __shared__ float t[32][33];
    const int b = blockIdx.z, s0 = blockIdx.x * 32, f0 = blockIdx.y * 32;
    const int tx = threadIdx.x, ty = threadIdx.y;
#pragma unroll
    for (int r = 0; r < 4; ++r) {
        int sl = ty + r * 8;
        t[sl][tx] = seq[((size_t)b * NS + s0 + sl) * NF + f0 + tx];
    }
    __syncthreads();
#pragma unroll
    for (int r = 0; r < 4; ++r) {
        int fl = ty + r * 8;
        float v = t[tx][fl];
        __nv_bfloat16 h = __float2bfloat16_rn(v);
        float l = v - __bfloat162float(h);
        size_t idx = ((size_t)b * NF + f0 + fl) * NS + s0 + tx;
        g_vth[idx] = h;
        g_vtl[idx] = __float2bfloat16_rn(l);
    }
}

// ---------------------------------------------------------------------------
// Kernel 3: mma.sync (bf16 HMMA) fused attention, DIRECT-LDS fragments.
// FIX vs R7: Q/K smem row stride was 136 bf16 (272B) for a 256-bf16 (512B)
// row -> rows overlapped. Now 264 bf16 = 132 words = 528B (mod-32-words = 4,
// conflict-free for the (4g + t4) fragment access pattern).
// ---------------------------------------------------------------------------
#define QKW      132   /* uint32 words per Q/K row: (256+8 pad) bf16 */
#define VPW      36    /* uint32 words per VT/P row: (64+8 pad) bf16 */
#define QH_OFF   0
#define QL_OFF   33792
#define KH_OFF   67584
#define KL_OFF   101376
#define VTH_OFF  135168
#define VTL_OFF  172032
#define PH_OFF   208896
#define PL_OFF   218112
#define DEN_OFF  227328
#define ASMEM    227840

__global__ __launch_bounds__(256, 1) void attn_mma(
    const float* __restrict__ cmask,
    const int*   __restrict__ causality,
    float* __restrict__ out)
{
    extern __shared__ char smem[];
    const int tid = threadIdx.x;
    const int wid = tid >> 5, lane = tid & 31;
    const int wr = wid & 3, wc = wid >> 2;   // q-band, f-half
    const int g = lane >> 2, t4 = lane & 3;  // fragment row, quad index
    const int b = blockIdx.y;
    const int causal = causality[0];

    const uint32_t* Qh32 = (const uint32_t*)(smem + QH_OFF);
    const uint32_t* Ql32 = (const uint32_t*)(smem + QL_OFF);
    const uint32_t* Kh32 = (const uint32_t*)(smem + KH_OFF);
    const uint32_t* Kl32 = (const uint32_t*)(smem + KL_OFF);
    const uint32_t* Vh32 = (const uint32_t*)(smem + VTH_OFF);
    const uint32_t* Vl32 = (const uint32_t*)(smem + VTL_OFF);
    const uint32_t* Ph32 = (const uint32_t*)(smem + PH_OFF);
    const uint32_t* Pl32 = (const uint32_t*)(smem + PL_OFF);
    float* den_s = (float*)(smem + DEN_OFF);

    const int ar0 = (16 * wr + g) * QKW;       // A rows (Q) in words
    const int ar1 = (16 * wr + g + 8) * QKW;
    const int pr0 = (16 * wr + g) * VPW;       // A rows (P)
    const int pr1 = (16 * wr + g + 8) * VPW;

    for (int half = 0; half < 2; ++half) {
        const int qt = half ? (31 - (int)blockIdx.x) : (int)blockIdx.x;
        const int q0 = qt * 64;

        __syncthreads();  // previous half fully done before Q restage

        // stage Q hi/lo (64 x 256 bf16 each), row stride QKW*2 bf16
        {
            const __nv_bfloat16* qh = g_qh + ((size_t)b * NS + q0) * NDK;
            const __nv_bfloat16* ql = g_ql + ((size_t)b * NS + q0) * NDK;
            for (int i = tid; i < 2048; i += 256) {
                int row = i >> 5, c8 = (i & 31) << 3;
                uint32_t off = (uint32_t)(row * (QKW * 2) + c8) * 2;
                *(uint4*)(smem + QH_OFF + off) = *(const uint4*)(qh + (size_t)row * NDK + c8);
                *(uint4*)(smem + QL_OFF + off) = *(const uint4*)(ql + (size_t)row * NDK + c8);
            }
        }

        float o[16][4];
#pragma unroll
        for (int j = 0; j < 16; ++j)
#pragma unroll
            for (int u = 0; u < 4; ++u) o[j][u] = 0.f;
        float denA = 0.f, denB = 0.f;

        const int kt0 = causal ? qt : 0;
        for (int kt = kt0; kt < 32; ++kt) {
            const int k0 = kt * 64;
            __syncthreads();  // prior tile's smem readers done; Q visible

            // stage K hi/lo (64 x 256) and V^T hi/lo (256 x 64)
            {
                const __nv_bfloat16* kh = g_kh + ((size_t)b * NS + k0) * NDK;
                const __nv_bfloat16* kl = g_kl + ((size_t)b * NS + k0) * NDK;
                for (int i = tid; i < 2048; i += 256) {
                    int row = i >> 5, c8 = (i & 31) << 3;
                    uint32_t off = (uint32_t)(row * (QKW * 2) + c8) * 2;
                    *(uint4*)(smem + KH_OFF + off) = *(const uint4*)(kh + (size_t)row * NDK + c8);
                    *(uint4*)(smem + KL_OFF + off) = *(const uint4*)(kl + (size_t)row * NDK + c8);
                }
                const __nv_bfloat16* vh = g_vth + (size_t)b * NF * NS + k0;
                const __nv_bfloat16* vl = g_vtl + (size_t)b * NF * NS + k0;
                for (int i = tid; i < 2048; i += 256) {
                    int f = i >> 3, k8 = (i & 7) << 3;
                    uint32_t off = (uint32_t)(f * (VPW * 2) + k8) * 2;
                    *(uint4*)(smem + VTH_OFF + off) = *(const uint4*)(vh + (size_t)f * NS + k8);
                    *(uint4*)(smem + VTL_OFF + off) = *(const uint4*)(vl + (size_t)f * NS + k8);
                }
            }

            // mask bits: 4 per n-group j -> {q1 c0, q1 c1, q2 c0, q2 c1}
            uint32_t mbits = 0;
            {
                const int q1 = q0 + 16 * wr + g;
                const int q2 = q1 + 8;
                const int kbase = k0 + 32 * wc + 2 * t4;
                const float* m1p = cmask + ((size_t)b * NS + q1) * NS;
                const float* m2p = cmask + ((size_t)b * NS + q2) * NS;
#pragma unroll
                for (int j = 0; j < 4; ++j) {
                    int kg = kbase + 8 * j;
                    float2 m1 = *(const float2*)(m1p + kg);
                    float2 m2 = *(const float2*)(m2p + kg);
                    uint32_t bits = 0;
                    if (m1.x > 0.f && (!causal || kg     >= q1)) bits |= 1u;
                    if (m1.y > 0.f && (!causal || kg + 1 >= q1)) bits |= 2u;
                    if (m2.x > 0.f && (!causal || kg     >= q2)) bits |= 4u;
                    if (m2.y > 0.f && (!causal || kg + 1 >= q2)) bits |= 8u;
                    mbits |= bits << (4 * j);
                }
            }
            __syncthreads();  // K/V staged

            // ---- Phase A: S = Q K^T (3 bf16 splits), direct-LDS fragments
            float s[4][4];
#pragma unroll
            for (int j = 0; j < 4; ++j)
#pragma unroll
                for (int u = 0; u < 4; ++u) s[j][u] = 0.f;

#pragma unroll 4
            for (int ks = 0; ks < 16; ++ks) {
                const int kw = ks * 8 + t4;
                uint32_t ah[4], al[4];
                ah[0] = Qh32[ar0 + kw];     ah[1] = Qh32[ar1 + kw];
                ah[2] = Qh32[ar0 + kw + 4]; ah[3] = Qh32[ar1 + kw + 4];
                al[0] = Ql32[ar0 + kw];     al[1] = Ql32[ar1 + kw];
                al[2] = Ql32[ar0 + kw + 4]; al[3] = Ql32[ar1 + kw + 4];
#pragma unroll
                for (int jp = 0; jp < 2; ++jp) {
                    const int br0 = (32 * wc + 16 * jp + g) * QKW;
                    const int br1 = (32 * wc + 16 * jp + 8 + g) * QKW;
                    uint32_t bh0 = Kh32[br0 + kw], bh1 = Kh32[br0 + kw + 4];
                    uint32_t bh2 = Kh32[br1 + kw], bh3 = Kh32[br1 + kw + 4];
                    uint32_t bl0 = Kl32[br0 + kw], bl1 = Kl32[br0 + kw + 4];
                    uint32_t bl2 = Kl32[br1 + kw], bl3 = Kl32[br1 + kw + 4];
                    mma_bf16(s[2 * jp],     ah, bh0, bh1);
                    mma_bf16(s[2 * jp],     al, bh0, bh1);
                    mma_bf16(s[2 * jp],     ah, bl0, bl1);
                    mma_bf16(s[2 * jp + 1], ah, bh2, bh3);
                    mma_bf16(s[2 * jp + 1], al, bh2, bh3);
                    mma_bf16(s[2 * jp + 1], ah, bl2, bl3);
                }
            }

            // ---- epilogue: p = exp(min(s/16,10)) masked; den; P hi/lo -> SMEM
            {
#pragma unroll
                for (int j = 0; j < 4; ++j) {
                    uint32_t bb = mbits >> (4 * j);
                    float p0 = (bb & 1u) ? __expf(fminf(s[j][0] * 0.0625f, 10.f)) : 0.f;
                    float p1 = (bb & 2u) ? __expf(fminf(s[j][1] * 0.0625f, 10.f)) : 0.f;
                    float p2 = (bb & 4u) ? __expf(fminf(s[j][2] * 0.0625f, 10.f)) : 0.f;
                    float p3 = (bb & 8u) ? __expf(fminf(s[j][3] * 0.0625f, 10.f)) : 0.f;
                    denA += p0 + p1;
                    denB += p2 + p3;
                    __nv_bfloat162 h1, l1, h2, l2;
                    h1.x = __float2bfloat16_rn(p0); h1.y = __float2bfloat16_rn(p1);
                    l1.x = __float2bfloat16_rn(p0 - __bfloat162float(h1.x));
                    l1.y = __float2bfloat16_rn(p1 - __bfloat162float(h1.y));
                    h2.x = __float2bfloat16_rn(p2); h2.y = __float2bfloat16_rn(p3);
                    l2.x = __float2bfloat16_rn(p2 - __bfloat162float(h2.x));
                    l2.y = __float2bfloat16_rn(p3 - __bfloat162float(h2.y));
                    int col = 32 * wc + 2 * t4 + 8 * j;
                    uint32_t w1 = (uint32_t)((16 * wr + g) * VPW + (col >> 1));
                    uint32_t w2 = (uint32_t)((16 * wr + g + 8) * VPW + (col >> 1));
                    ((uint32_t*)(smem + PH_OFF))[w1] = *(uint32_t*)&h1;
                    ((uint32_t*)(smem + PL_OFF))[w1] = *(uint32_t*)&l1;
                    ((uint32_t*)(smem + PH_OFF))[w2] = *(uint32_t*)&h2;
                    ((uint32_t*)(smem + PL_OFF))[w2] = *(uint32_t*)&l2;
                }
            }
            __syncthreads();  // P visible

            // ---- Phase B: O += P V^T (3 bf16 splits), direct-LDS fragments
#pragma unroll
            for (int ks = 0; ks < 4; ++ks) {
                const int kw = ks * 8 + t4;
                uint32_t ah[4], al[4];
                ah[0] = Ph32[pr0 + kw];     ah[1] = Ph32[pr1 + kw];
                ah[2] = Ph32[pr0 + kw + 4]; ah[3] = Ph32[pr1 + kw + 4];
                al[0] = Pl32[pr0 + kw];     al[1] = Pl32[pr1 + kw];
                al[2] = Pl32[pr0 + kw + 4]; al[3] = Pl32[pr1 + kw + 4];
#pragma unroll
                for (int jp = 0; jp < 8; ++jp) {
                    const int vr0 = (128 * wc + 16 * jp + g) * VPW;
                    const int vr1 = (128 * wc + 16 * jp + 8 + g) * VPW;
                    uint32_t bh0 = Vh32[vr0 + kw], bh1 = Vh32[vr0 + kw + 4];
                    uint32_t bh2 = Vh32[vr1 + kw], bh3 = Vh32[vr1 + kw + 4];
                    uint32_t bl0 = Vl32[vr0 + kw], bl1 = Vl32[vr0 + kw + 4];
                    uint32_t bl2 = Vl32[vr1 + kw], bl3 = Vl32[vr1 + kw + 4];
                    mma_bf16(o[2 * jp],     ah, bh0, bh1);
                    mma_bf16(o[2 * jp],     al, bh0, bh1);
                    mma_bf16(o[2 * jp],     ah, bl0, bl1);
                    mma_bf16(o[2 * jp + 1], ah, bh2, bh3);
                    mma_bf16(o[2 * jp + 1], al, bh2, bh3);
                    mma_bf16(o[2 * jp + 1], ah, bl2, bl3);
                }
            }
        }

        // ---- den reduction within quads (same q-row), then across f-warps
        denA += __shfl_xor_sync(0xffffffffu, denA, 1);
        denA += __shfl_xor_sync(0xffffffffu, denA, 2);
        denB += __shfl_xor_sync(0xffffffffu, denB, 1);
        denB += __shfl_xor_sync(0xffffffffu, denB, 2);
        __syncthreads();  // last tile's readers done before den_s write
        if (t4 == 0) {
            den_s[wc * 64 + 16 * wr + g] = denA;
            den_s[wc * 64 + 16 * wr + g + 8] = denB;
        }
        __syncthreads();

        // ---- output: O / den
        {
            const int q1row = 16 * wr + g;
            const float inv1 = 1.0f / (den_s[q1row] + den_s[64 + q1row]);
            const float inv2 = 1.0f / (den_s[q1row + 8] + den_s[64 + q1row + 8]);
            float* o1 = out + ((size_t)b * NS + q0 + q1row) * NF;
            float* o2 = out + ((size_t)b * NS + q0 + q1row + 8) * NF;
#pragma unroll
            for (int j2 = 0; j2 < 16; ++j2) {
                int f = 128 * wc + 8 * j2 + 2 * t4;
                float2 v1, v2;
                v1.x = o[j2][0] * inv1; v1.y = o[j2][1] * inv1;
                v2.x = o[j2][2] * inv2; v2.y = o[j2][3] * inv2;
                *(float2*)(o1 + f) = v1;
                *(float2*)(o2 + f) = v2;
            }
        }
    }
}

// ---------------------------------------------------------------------------
extern "C" void kernel_launch(void* const* d_in, const int* in_sizes, int n_in,
                              void* d_out, int out_size)
{
    const float* seq  = (const float*)d_in[0];
    const float* pos  = (const float*)d_in[1];
    const float* tim  = (const float*)d_in[2];
    const float* Wq   = (const float*)d_in[3];
    const float* Wk   = (const float*)d_in[4];
    const float* cm   = (const float*)d_in[5];
    const int*   caus = (const int*)d_in[6];
    float* out = (float*)d_out;

    cudaFuncSetAttribute(attn_mma, cudaFuncAttributeMaxDynamicSharedMemorySize, ASMEM);

    dim3 gp(NB * NS / 64, NDK / 64, 2);
    proj_kernel<<<gp, 256>>>(seq, pos, tim, Wq, Wk);

    dim3 gv(NS / 32, NF / 32, NB);
    vsplit_kernel<<<gv, dim3(32, 8)>>>(seq);

    dim3 ga(16, NB);   // 128 CTAs, 33 key-tiles each (causal), 1 wave
    attn_mma<<<ga, 256, ASMEM>>>(cm, caus, out);
}

// round 10
// speedup vs baseline: 4.5591x; 1.1138x over previous
#include <cuda_runtime.h>
#include <cuda_bf16.h>
#include <cstdint>

#define NB 8
#define NS 2048
#define NF 256
#define NE 64
#define NDK 256
#define NIN 384

__device__ __forceinline__ void mma_bf16(float d[4], const uint32_t a[4],
                                         uint32_t b0, uint32_t b1) {
    asm volatile(
        "mma.sync.aligned.m16n8k16.row.col.f32.bf16.bf16.f32 "
        "{%0,%1,%2,%3}, {%4,%5,%6,%7}, {%8,%9}, {%0,%1,%2,%3};"
        : "+f"(d[0]), "+f"(d[1]), "+f"(d[2]), "+f"(d[3])
        : "r"(a[0]), "r"(a[1]), "r"(a[2]), "r"(a[3]), "r"(b0), "r"(b1));
}

__device__ __forceinline__ uint32_t pack_hi2(float a, float b, uint32_t& lo) {
    __nv_bfloat162 h, l;
    h.x = __float2bfloat16_rn(a); h.y = __float2bfloat16_rn(b);
    l.x = __float2bfloat16_rn(a - __bfloat162float(h.x));
    l.y = __float2bfloat16_rn(b - __bfloat162float(h.y));
    lo = *(uint32_t*)&l;
    return *(uint32_t*)&h;
}

// ---------------------------------------------------------------------------
// Global scratch (bf16 hi/lo splits)
// ---------------------------------------------------------------------------
__device__ __nv_bfloat16 g_qh[(size_t)NB * NS * NDK];
__device__ __nv_bfloat16 g_ql[(size_t)NB * NS * NDK];
__device__ __nv_bfloat16 g_kh[(size_t)NB * NS * NDK];
__device__ __nv_bfloat16 g_kl[(size_t)NB * NS * NDK];
__device__ __nv_bfloat16 g_vth[(size_t)NB * NF * NS];  // [b][f][s]
__device__ __nv_bfloat16 g_vtl[(size_t)NB * NF * NS];

// ---------------------------------------------------------------------------
// Kernel 1: Q/K projection via bf16-split HMMA.
// C[16384,256] = X[16384,384] @ W^T, X = concat(seq,pos,time) (fp32, split
// to bf16 hi/lo during staging).  CTA tile 128m x 128n, K in 3 chunks of 128.
// 8 warps = 4 m-bands (32m) x 2 n-halves (64n).  3-term split per product.
// Row stride 136 bf16 = 68 words == 4 mod 32 -> conflict-free fragment LDS.
// ---------------------------------------------------------------------------
#define XW      68       /* words per staged row (128 bf16 + 8 pad) */
#define XH_OFF  0
#define XL_OFF  34816
#define WH_OFF  69632
#define WL_OFF  104448
#define PSMEM   139264

__global__ __launch_bounds__(256, 1) void proj_mma(
    const float* __restrict__ seq, const float* __restrict__ pos,
    const float* __restrict__ tim, const float* __restrict__ Wq,
    const float* __restrict__ Wk)
{
    extern __shared__ char smem[];
    const int tid = threadIdx.x, wid = tid >> 5, lane = tid & 31;
    const int wr = wid & 3, wc = wid >> 2;
    const int g = lane >> 2, t4 = lane & 3;
    const int m0 = blockIdx.x * 128, n0 = blockIdx.y * 128;
    const float* W = blockIdx.z ? Wk : Wq;
    __nv_bfloat16* dh = blockIdx.z ? g_kh : g_qh;
    __nv_bfloat16* dl = blockIdx.z ? g_kl : g_ql;

    uint32_t* Xh = (uint32_t*)(smem + XH_OFF);
    uint32_t* Xl = (uint32_t*)(smem + XL_OFF);
    uint32_t* Wh = (uint32_t*)(smem + WH_OFF);
    uint32_t* Wl = (uint32_t*)(smem + WL_OFF);

    float acc[2][8][4];
#pragma unroll
    for (int mi = 0; mi < 2; ++mi)
#pragma unroll
        for (int jn = 0; jn < 8; ++jn)
#pragma unroll
            for (int u = 0; u < 4; ++u) acc[mi][jn][u] = 0.f;

    for (int ch = 0; ch < 3; ++ch) {
        __syncthreads();  // previous chunk's fragment readers done
        // stage X[128 rows, 128 cols] and W[128 rows, 128 cols] fp32 -> hi/lo
        for (int i = tid; i < 4096; i += 256) {
            int row = i >> 5, cc = (i & 31) * 4;
            int col = ch * 128 + cc;
            float4 xv;
            if (col < 256)
                xv = *(const float4*)(seq + (size_t)(m0 + row) * NF + col);
            else if (col < 320)
                xv = *(const float4*)(pos + (size_t)(m0 + row) * NE + (col - 256));
            else
                xv = *(const float4*)(tim + (size_t)(m0 + row) * NE + (col - 320));
            uint32_t l0, l1;
            uint32_t h0 = pack_hi2(xv.x, xv.y, l0);
            uint32_t h1 = pack_hi2(xv.z, xv.w, l1);
            int w = row * XW + (cc >> 1);
            *(uint2*)(Xh + w) = make_uint2(h0, h1);
            *(uint2*)(Xl + w) = make_uint2(l0, l1);

            float4 wv = *(const float4*)(W + (size_t)(n0 + row) * NIN + col);
            uint32_t wl0, wl1;
            uint32_t wh0 = pack_hi2(wv.x, wv.y, wl0);
            uint32_t wh1 = pack_hi2(wv.z, wv.w, wl1);
            *(uint2*)(Wh + w) = make_uint2(wh0, wh1);
            *(uint2*)(Wl + w) = make_uint2(wl0, wl1);
        }
        __syncthreads();

#pragma unroll
        for (int ks = 0; ks < 8; ++ks) {
            const int kw = ks * 8 + t4;
            uint32_t ah[2][4], al[2][4];
#pragma unroll
            for (int mi = 0; mi < 2; ++mi) {
                int r0 = (32 * wr + 16 * mi + g) * XW, r1 = r0 + 8 * XW;
                ah[mi][0] = Xh[r0 + kw];     ah[mi][1] = Xh[r1 + kw];
                ah[mi][2] = Xh[r0 + kw + 4]; ah[mi][3] = Xh[r1 + kw + 4];
                al[mi][0] = Xl[r0 + kw];     al[mi][1] = Xl[r1 + kw];
                al[mi][2] = Xl[r0 + kw + 4]; al[mi][3] = Xl[r1 + kw + 4];
            }
#pragma unroll
            for (int jn = 0; jn < 8; ++jn) {
                int br = (64 * wc + 8 * jn + g) * XW;
                uint32_t bh0 = Wh[br + kw], bh1 = Wh[br + kw + 4];
                uint32_t bl0 = Wl[br + kw], bl1 = Wl[br + kw + 4];
#pragma unroll
                for (int mi = 0; mi < 2; ++mi) {
                    mma_bf16(acc[mi][jn], ah[mi], bh0, bh1);
                    mma_bf16(acc[mi][jn], al[mi], bh0, bh1);
                    mma_bf16(acc[mi][jn], ah[mi], bl0, bl1);
                }
            }
        }
    }

    // output: split fp32 accumulators to bf16 hi/lo, write packed pairs
#pragma unroll
    for (int mi = 0; mi < 2; ++mi) {
        int m1 = m0 + 32 * wr + 16 * mi + g;
        int m2 = m1 + 8;
#pragma unroll
        for (int jn = 0; jn < 8; ++jn) {
            int n = n0 + 64 * wc + 8 * jn + 2 * t4;
            uint32_t lo1, lo2;
            uint32_t hi1 = pack_hi2(acc[mi][jn][0], acc[mi][jn][1], lo1);
            uint32_t hi2 = pack_hi2(acc[mi][jn][2], acc[mi][jn][3], lo2);
            *(uint32_t*)(dh + (size_t)m1 * NDK + n) = hi1;
            *(uint32_t*)(dl + (size_t)m1 * NDK + n) = lo1;
            *(uint32_t*)(dh + (size_t)m2 * NDK + n) = hi2;
            *(uint32_t*)(dl + (size_t)m2 * NDK + n) = lo2;
        }
    }
}

// ---------------------------------------------------------------------------
// Kernel 2: V = seq transpose + bf16 split: g_vt{h,l}[b][f][s]
// ---------------------------------------------------------------------------
__global__ __launch_bounds__(256) void vsplit_kernel(const float* __restrict__ seq)
{
    __shared__ float t[32][33];
    const int b = blockIdx.z, s0 = blockIdx.x * 32, f0 = blockIdx.y * 32;
    const int tx = threadIdx.x, ty = threadIdx.y;
#pragma unroll
    for (int r = 0; r < 4; ++r) {
        int sl = ty + r * 8;
        t[sl][tx] = seq[((size_t)b * NS + s0 + sl) * NF + f0 + tx];
    }
    __syncthreads();
#pragma unroll
    for (int r = 0; r < 4; ++r) {
        int fl = ty + r * 8;
        float v = t[tx][fl];
        __nv_bfloat16 h = __float2bfloat16_rn(v);
        float l = v - __bfloat162float(h);
        size_t idx = ((size_t)b * NF + f0 + fl) * NS + s0 + tx;
        g_vth[idx] = h;
        g_vtl[idx] = __float2bfloat16_rn(l);
    }
}

// ---------------------------------------------------------------------------
// Kernel 3: mma.sync (bf16 HMMA) fused attention, DIRECT-LDS fragments.
// (unchanged from R8 — passing at rel_err 6.2e-6)
// ---------------------------------------------------------------------------
#define QKW      132   /* uint32 words per Q/K row: (256+8 pad) bf16 */
#define VPW      36    /* uint32 words per VT/P row: (64+8 pad) bf16 */
#define QH_OFF   0
#define QL_OFF   33792
#define KH_OFF   67584
#define KL_OFF   101376
#define VTH_OFF  135168
#define VTL_OFF  172032
#define PH_OFF   208896
#define PL_OFF   218112
#define DEN_OFF  227328
#define ASMEM    227840

__global__ __launch_bounds__(256, 1) void attn_mma(
    const float* __restrict__ cmask,
    const int*   __restrict__ causality,
    float* __restrict__ out)
{
    extern __shared__ char smem[];
    const int tid = threadIdx.x;
    const int wid = tid >> 5, lane = tid & 31;
    const int wr = wid & 3, wc = wid >> 2;   // q-band, f-half
    const int g = lane >> 2, t4 = lane & 3;  // fragment row, quad index
    const int b = blockIdx.y;
    const int causal = causality[0];

    const uint32_t* Qh32 = (const uint32_t*)(smem + QH_OFF);
    const uint32_t* Ql32 = (const uint32_t*)(smem + QL_OFF);
    const uint32_t* Kh32 = (const uint32_t*)(smem + KH_OFF);
    const uint32_t* Kl32 = (const uint32_t*)(smem + KL_OFF);
    const uint32_t* Vh32 = (const uint32_t*)(smem + VTH_OFF);
    const uint32_t* Vl32 = (const uint32_t*)(smem + VTL_OFF);
    const uint32_t* Ph32 = (const uint32_t*)(smem + PH_OFF);
    const uint32_t* Pl32 = (const uint32_t*)(smem + PL_OFF);
    float* den_s = (float*)(smem + DEN_OFF);

    const int ar0 = (16 * wr + g) * QKW;
    const int ar1 = (16 * wr + g + 8) * QKW;
    const int pr0 = (16 * wr + g) * VPW;
    const int pr1 = (16 * wr + g + 8) * VPW;

    for (int half = 0; half < 2; ++half) {
        const int qt = half ? (31 - (int)blockIdx.x) : (int)blockIdx.x;
        const int q0 = qt * 64;

        __syncthreads();

        {
            const __nv_bfloat16* qh = g_qh + ((size_t)b * NS + q0) * NDK;
            const __nv_bfloat16* ql = g_ql + ((size_t)b * NS + q0) * NDK;
            for (int i = tid; i < 2048; i += 256) {
                int row = i >> 5, c8 = (i & 31) << 3;
                uint32_t off = (uint32_t)(row * (QKW * 2) + c8) * 2;
                *(uint4*)(smem + QH_OFF + off) = *(const uint4*)(qh + (size_t)row * NDK + c8);
                *(uint4*)(smem + QL_OFF + off) = *(const uint4*)(ql + (size_t)row * NDK + c8);
            }
        }

        float o[16][4];
#pragma unroll
        for (int j = 0; j < 16; ++j)
#pragma unroll
            for (int u = 0; u < 4; ++u) o[j][u] = 0.f;
        float denA = 0.f, denB = 0.f;

        const int kt0 = causal ? qt : 0;
        for (int kt = kt0; kt < 32; ++kt) {
            const int k0 = kt * 64;
            __syncthreads();

            {
                const __nv_bfloat16* kh = g_kh + ((size_t)b * NS + k0) * NDK;
                const __nv_bfloat16* kl = g_kl + ((size_t)b * NS + k0) * NDK;
                for (int i = tid; i < 2048; i += 256) {
                    int row = i >> 5, c8 = (i & 31) << 3;
                    uint32_t off = (uint32_t)(row * (QKW * 2) + c8) * 2;
                    *(uint4*)(smem + KH_OFF + off) = *(const uint4*)(kh + (size_t)row * NDK + c8);
                    *(uint4*)(smem + KL_OFF + off) = *(const uint4*)(kl + (size_t)row * NDK + c8);
                }
                const __nv_bfloat16* vh = g_vth + (size_t)b * NF * NS + k0;
                const __nv_bfloat16* vl = g_vtl + (size_t)b * NF * NS + k0;
                for (int i = tid; i < 2048; i += 256) {
                    int f = i >> 3, k8 = (i & 7) << 3;
                    uint32_t off = (uint32_t)(f * (VPW * 2) + k8) * 2;
                    *(uint4*)(smem + VTH_OFF + off) = *(const uint4*)(vh + (size_t)f * NS + k8);
                    *(uint4*)(smem + VTL_OFF + off) = *(const uint4*)(vl + (size_t)f * NS + k8);
                }
            }

            uint32_t mbits = 0;
            {
                const int q1 = q0 + 16 * wr + g;
                const int q2 = q1 + 8;
                const int kbase = k0 + 32 * wc + 2 * t4;
                const float* m1p = cmask + ((size_t)b * NS + q1) * NS;
                const float* m2p = cmask + ((size_t)b * NS + q2) * NS;
#pragma unroll
                for (int j = 0; j < 4; ++j) {
                    int kg = kbase + 8 * j;
                    float2 m1 = *(const float2*)(m1p + kg);
                    float2 m2 = *(const float2*)(m2p + kg);
                    uint32_t bits = 0;
                    if (m1.x > 0.f && (!causal || kg     >= q1)) bits |= 1u;
                    if (m1.y > 0.f && (!causal || kg + 1 >= q1)) bits |= 2u;
                    if (m2.x > 0.f && (!causal || kg     >= q2)) bits |= 4u;
                    if (m2.y > 0.f && (!causal || kg + 1 >= q2)) bits |= 8u;
                    mbits |= bits << (4 * j);
                }
            }
            __syncthreads();

            float s[4][4];
#pragma unroll
            for (int j = 0; j < 4; ++j)
#pragma unroll
                for (int u = 0; u < 4; ++u) s[j][u] = 0.f;

#pragma unroll 4
            for (int ks = 0; ks < 16; ++ks) {
                const int kw = ks * 8 + t4;
                uint32_t ah[4], al[4];
                ah[0] = Qh32[ar0 + kw];     ah[1] = Qh32[ar1 + kw];
                ah[2] = Qh32[ar0 + kw + 4]; ah[3] = Qh32[ar1 + kw + 4];
                al[0] = Ql32[ar0 + kw];     al[1] = Ql32[ar1 + kw];
                al[2] = Ql32[ar0 + kw + 4]; al[3] = Ql32[ar1 + kw + 4];
#pragma unroll
                for (int jp = 0; jp < 2; ++jp) {
                    const int br0 = (32 * wc + 16 * jp + g) * QKW;
                    const int br1 = (32 * wc + 16 * jp + 8 + g) * QKW;
                    uint32_t bh0 = Kh32[br0 + kw], bh1 = Kh32[br0 + kw + 4];
                    uint32_t bh2 = Kh32[br1 + kw], bh3 = Kh32[br1 + kw + 4];
                    uint32_t bl0 = Kl32[br0 + kw], bl1 = Kl32[br0 + kw + 4];
                    uint32_t bl2 = Kl32[br1 + kw], bl3 = Kl32[br1 + kw + 4];
                    mma_bf16(s[2 * jp],     ah, bh0, bh1);
                    mma_bf16(s[2 * jp],     al, bh0, bh1);
                    mma_bf16(s[2 * jp],     ah, bl0, bl1);
                    mma_bf16(s[2 * jp + 1], ah, bh2, bh3);
                    mma_bf16(s[2 * jp + 1], al, bh2, bh3);
                    mma_bf16(s[2 * jp + 1], ah, bl2, bl3);
                }
            }

            {
#pragma unroll
                for (int j = 0; j < 4; ++j) {
                    uint32_t bb = mbits >> (4 * j);
                    float p0 = (bb & 1u) ? __expf(fminf(s[j][0] * 0.0625f, 10.f)) : 0.f;
                    float p1 = (bb & 2u) ? __expf(fminf(s[j][1] * 0.0625f, 10.f)) : 0.f;
                    float p2 = (bb & 4u) ? __expf(fminf(s[j][2] * 0.0625f, 10.f)) : 0.f;
                    float p3 = (bb & 8u) ? __expf(fminf(s[j][3] * 0.0625f, 10.f)) : 0.f;
                    denA += p0 + p1;
                    denB += p2 + p3;
                    uint32_t lo1, lo2;
                    uint32_t hi1 = pack_hi2(p0, p1, lo1);
                    uint32_t hi2 = pack_hi2(p2, p3, lo2);
                    int col = 32 * wc + 2 * t4 + 8 * j;
                    uint32_t w1 = (uint32_t)((16 * wr + g) * VPW + (col >> 1));
                    uint32_t w2 = (uint32_t)((16 * wr + g + 8) * VPW + (col >> 1));
                    ((uint32_t*)(smem + PH_OFF))[w1] = hi1;
                    ((uint32_t*)(smem + PL_OFF))[w1] = lo1;
                    ((uint32_t*)(smem + PH_OFF))[w2] = hi2;
                    ((uint32_t*)(smem + PL_OFF))[w2] = lo2;
                }
            }
            __syncthreads();

#pragma unroll
            for (int ks = 0; ks < 4; ++ks) {
                const int kw = ks * 8 + t4;
                uint32_t ah[4], al[4];
                ah[0] = Ph32[pr0 + kw];     ah[1] = Ph32[pr1 + kw];
                ah[2] = Ph32[pr0 + kw + 4]; ah[3] = Ph32[pr1 + kw + 4];
                al[0] = Pl32[pr0 + kw];     al[1] = Pl32[pr1 + kw];
                al[2] = Pl32[pr0 + kw + 4]; al[3] = Pl32[pr1 + kw + 4];
#pragma unroll
                for (int jp = 0; jp < 8; ++jp) {
                    const int vr0 = (128 * wc + 16 * jp + g) * VPW;
                    const int vr1 = (128 * wc + 16 * jp + 8 + g) * VPW;
                    uint32_t bh0 = Vh32[vr0 + kw], bh1 = Vh32[vr0 + kw + 4];
                    uint32_t bh2 = Vh32[vr1 + kw], bh3 = Vh32[vr1 + kw + 4];
                    uint32_t bl0 = Vl32[vr0 + kw], bl1 = Vl32[vr0 + kw + 4];
                    uint32_t bl2 = Vl32[vr1 + kw], bl3 = Vl32[vr1 + kw + 4];
                    mma_bf16(o[2 * jp],     ah, bh0, bh1);
                    mma_bf16(o[2 * jp],     al, bh0, bh1);
                    mma_bf16(o[2 * jp],     ah, bl0, bl1);
                    mma_bf16(o[2 * jp + 1], ah, bh2, bh3);
                    mma_bf16(o[2 * jp + 1], al, bh2, bh3);
                    mma_bf16(o[2 * jp + 1], ah, bl2, bl3);
                }
            }
        }

        denA += __shfl_xor_sync(0xffffffffu, denA, 1);
        denA += __shfl_xor_sync(0xffffffffu, denA, 2);
        denB += __shfl_xor_sync(0xffffffffu, denB, 1);
        denB += __shfl_xor_sync(0xffffffffu, denB, 2);
        __syncthreads();
        if (t4 == 0) {
            den_s[wc * 64 + 16 * wr + g] = denA;
            den_s[wc * 64 + 16 * wr + g + 8] = denB;
        }
        __syncthreads();

        {
            const int q1row = 16 * wr + g;
            const float inv1 = 1.0f / (den_s[q1row] + den_s[64 + q1row]);
            const float inv2 = 1.0f / (den_s[q1row + 8] + den_s[64 + q1row + 8]);
            float* o1 = out + ((size_t)b * NS + q0 + q1row) * NF;
            float* o2 = out + ((size_t)b * NS + q0 + q1row + 8) * NF;
#pragma unroll
            for (int j2 = 0; j2 < 16; ++j2) {
                int f = 128 * wc + 8 * j2 + 2 * t4;
                float2 v1, v2;
                v1.x = o[j2][0] * inv1; v1.y = o[j2][1] * inv1;
                v2.x = o[j2][2] * inv2; v2.y = o[j2][3] * inv2;
                *(float2*)(o1 + f) = v1;
                *(float2*)(o2 + f) = v2;
            }
        }
    }
}

// ---------------------------------------------------------------------------
extern "C" void kernel_launch(void* const* d_in, const int* in_sizes, int n_in,
                              void* d_out, int out_size)
{
    const float* seq  = (const float*)d_in[0];
    const float* pos  = (const float*)d_in[1];
    const float* tim  = (const float*)d_in[2];
    const float* Wq   = (const float*)d_in[3];
    const float* Wk   = (const float*)d_in[4];
    const float* cm   = (const float*)d_in[5];
    const int*   caus = (const int*)d_in[6];
    float* out = (float*)d_out;

    cudaFuncSetAttribute(proj_mma, cudaFuncAttributeMaxDynamicSharedMemorySize, PSMEM);
    cudaFuncSetAttribute(attn_mma, cudaFuncAttributeMaxDynamicSharedMemorySize, ASMEM);

    dim3 gp(NB * NS / 128, NDK / 128, 2);   // (128, 2, 2) = 512 CTAs
    proj_mma<<<gp, 256, PSMEM>>>(seq, pos, tim, Wq, Wk);

    dim3 gv(NS / 32, NF / 32, NB);
    vsplit_kernel<<<gv, dim3(32, 8)>>>(seq);

    dim3 ga(16, NB);   // 128 CTAs, 33 key-tiles each (causal), 1 wave
    attn_mma<<<ga, 256, ASMEM>>>(cm, caus, out);
}

// round 11
// speedup vs baseline: 5.7895x; 1.2699x over previous
#include <cuda_runtime.h>
#include <cuda_bf16.h>
#include <cstdint>

#define NB 8
#define NS 2048
#define NF 256
#define NE 64
#define NDK 256
#define NIN 384

__device__ __forceinline__ void mma_bf16(float d[4], const uint32_t a[4],
                                         uint32_t b0, uint32_t b1) {
    asm volatile(
        "mma.sync.aligned.m16n8k16.row.col.f32.bf16.bf16.f32 "
        "{%0,%1,%2,%3}, {%4,%5,%6,%7}, {%8,%9}, {%0,%1,%2,%3};"
        : "+f"(d[0]), "+f"(d[1]), "+f"(d[2]), "+f"(d[3])
        : "r"(a[0]), "r"(a[1]), "r"(a[2]), "r"(a[3]), "r"(b0), "r"(b1));
}

__device__ __forceinline__ uint32_t pack_hi2(float a, float b, uint32_t& lo) {
    __nv_bfloat162 h, l;
    h.x = __float2bfloat16_rn(a); h.y = __float2bfloat16_rn(b);
    l.x = __float2bfloat16_rn(a - __bfloat162float(h.x));
    l.y = __float2bfloat16_rn(b - __bfloat162float(h.y));
    lo = *(uint32_t*)&l;
    return *(uint32_t*)&h;
}

__device__ __forceinline__ uint32_t smem_u32(const void* p) {
    uint32_t a;
    asm("{ .reg .u64 t; cvta.to.shared.u64 t, %1; cvt.u32.u64 %0, t; }"
        : "=r"(a) : "l"(p));
    return a;
}

#define CP16(dst, src) \
    asm volatile("cp.async.cg.shared.global [%0], [%1], 16;" \
                 :: "r"(dst), "l"(src))
#define CP_COMMIT()   asm volatile("cp.async.commit_group;" ::: "memory")
#define CP_WAIT_ALL() asm volatile("cp.async.wait_all;" ::: "memory")

// ---------------------------------------------------------------------------
// Global scratch (bf16 hi/lo splits)
// ---------------------------------------------------------------------------
__device__ __nv_bfloat16 g_qh[(size_t)NB * NS * NDK];
__device__ __nv_bfloat16 g_ql[(size_t)NB * NS * NDK];
__device__ __nv_bfloat16 g_kh[(size_t)NB * NS * NDK];
__device__ __nv_bfloat16 g_kl[(size_t)NB * NS * NDK];
__device__ __nv_bfloat16 g_vth[(size_t)NB * NF * NS];  // [b][f][s]
__device__ __nv_bfloat16 g_vtl[(size_t)NB * NF * NS];

// ---------------------------------------------------------------------------
// Kernel 1: Q/K projection via bf16-split HMMA.
// K chunk = 64 (6 chunks) -> smem 72KB -> 2 CTAs/SM for stage/MMA overlap.
// Each chunk maps to exactly one source tensor (0-3: seq, 4: pos, 5: tim).
// ---------------------------------------------------------------------------
#define XW      36       /* words per staged row (64 bf16 + 8 pad) */
#define XH_OFF  0
#define XL_OFF  18432
#define WH_OFF  36864
#define WL_OFF  55296
#define PSMEM   73728

__global__ __launch_bounds__(256, 2) void proj_mma(
    const float* __restrict__ seq, const float* __restrict__ pos,
    const float* __restrict__ tim, const float* __restrict__ Wq,
    const float* __restrict__ Wk)
{
    extern __shared__ char smem[];
    const int tid = threadIdx.x, wid = tid >> 5, lane = tid & 31;
    const int wr = wid & 3, wc = wid >> 2;
    const int g = lane >> 2, t4 = lane & 3;
    const int m0 = blockIdx.x * 128, n0 = blockIdx.y * 128;
    const float* W = blockIdx.z ? Wk : Wq;
    __nv_bfloat16* dh = blockIdx.z ? g_kh : g_qh;
    __nv_bfloat16* dl = blockIdx.z ? g_kl : g_ql;

    uint32_t* Xh = (uint32_t*)(smem + XH_OFF);
    uint32_t* Xl = (uint32_t*)(smem + XL_OFF);
    uint32_t* Wh = (uint32_t*)(smem + WH_OFF);
    uint32_t* Wl = (uint32_t*)(smem + WL_OFF);

    float acc[2][8][4];
#pragma unroll
    for (int mi = 0; mi < 2; ++mi)
#pragma unroll
        for (int jn = 0; jn < 8; ++jn)
#pragma unroll
            for (int u = 0; u < 4; ++u) acc[mi][jn][u] = 0.f;

    for (int ch = 0; ch < 6; ++ch) {
        const float* xsrc; int xw, xcol;
        if (ch < 4)      { xsrc = seq; xw = NF; xcol = ch * 64; }
        else if (ch < 5) { xsrc = pos; xw = NE; xcol = 0; }
        else             { xsrc = tim; xw = NE; xcol = 0; }
        const int wcol = ch * 64;

        __syncthreads();  // previous chunk's fragment readers done
        // stage X[128, 64] and W[128, 64] fp32 -> bf16 hi/lo (8 iters each)
        for (int i = tid; i < 2048; i += 256) {
            int row = i >> 4, cc = (i & 15) * 4;
            float4 xv = *(const float4*)(xsrc + (size_t)(m0 + row) * xw + xcol + cc);
            uint32_t l0, l1;
            uint32_t h0 = pack_hi2(xv.x, xv.y, l0);
            uint32_t h1 = pack_hi2(xv.z, xv.w, l1);
            int w = row * XW + (cc >> 1);
            *(uint2*)(Xh + w) = make_uint2(h0, h1);
            *(uint2*)(Xl + w) = make_uint2(l0, l1);

            float4 wv = *(const float4*)(W + (size_t)(n0 + row) * NIN + wcol + cc);
            uint32_t wl0, wl1;
            uint32_t wh0 = pack_hi2(wv.x, wv.y, wl0);
            uint32_t wh1 = pack_hi2(wv.z, wv.w, wl1);
            *(uint2*)(Wh + w) = make_uint2(wh0, wh1);
            *(uint2*)(Wl + w) = make_uint2(wl0, wl1);
        }
        __syncthreads();

#pragma unroll
        for (int ks = 0; ks < 4; ++ks) {
            const int kw = ks * 8 + t4;
            uint32_t ah[2][4], al[2][4];
#pragma unroll
            for (int mi = 0; mi < 2; ++mi) {
                int r0 = (32 * wr + 16 * mi + g) * XW, r1 = r0 + 8 * XW;
                ah[mi][0] = Xh[r0 + kw];     ah[mi][1] = Xh[r1 + kw];
                ah[mi][2] = Xh[r0 + kw + 4]; ah[mi][3] = Xh[r1 + kw + 4];
                al[mi][0] = Xl[r0 + kw];     al[mi][1] = Xl[r1 + kw];
                al[mi][2] = Xl[r0 + kw + 4]; al[mi][3] = Xl[r1 + kw + 4];
            }
#pragma unroll
            for (int jn = 0; jn < 8; ++jn) {
                int br = (64 * wc + 8 * jn + g) * XW;
                uint32_t bh0 = Wh[br + kw], bh1 = Wh[br + kw + 4];
                uint32_t bl0 = Wl[br + kw], bl1 = Wl[br + kw + 4];
#pragma unroll
                for (int mi = 0; mi < 2; ++mi) {
                    mma_bf16(acc[mi][jn], ah[mi], bh0, bh1);
                    mma_bf16(acc[mi][jn], al[mi], bh0, bh1);
                    mma_bf16(acc[mi][jn], ah[mi], bl0, bl1);
                }
            }
        }
    }

    // output: split fp32 accumulators to bf16 hi/lo, write packed pairs
#pragma unroll
    for (int mi = 0; mi < 2; ++mi) {
        int m1 = m0 + 32 * wr + 16 * mi + g;
        int m2 = m1 + 8;
#pragma unroll
        for (int jn = 0; jn < 8; ++jn) {
            int n = n0 + 64 * wc + 8 * jn + 2 * t4;
            uint32_t lo1, lo2;
            uint32_t hi1 = pack_hi2(acc[mi][jn][0], acc[mi][jn][1], lo1);
            uint32_t hi2 = pack_hi2(acc[mi][jn][2], acc[mi][jn][3], lo2);
            *(uint32_t*)(dh + (size_t)m1 * NDK + n) = hi1;
            *(uint32_t*)(dl + (size_t)m1 * NDK + n) = lo1;
            *(uint32_t*)(dh + (size_t)m2 * NDK + n) = hi2;
            *(uint32_t*)(dl + (size_t)m2 * NDK + n) = lo2;
        }
    }
}

// ---------------------------------------------------------------------------
// Kernel 2: V = seq transpose + bf16 split: g_vt{h,l}[b][f][s]
// ---------------------------------------------------------------------------
__global__ __launch_bounds__(256) void vsplit_kernel(const float* __restrict__ seq)
{
    __shared__ float t[32][33];
    const int b = blockIdx.z, s0 = blockIdx.x * 32, f0 = blockIdx.y * 32;
    const int tx = threadIdx.x, ty = threadIdx.y;
#pragma unroll
    for (int r = 0; r < 4; ++r) {
        int sl = ty + r * 8;
        t[sl][tx] = seq[((size_t)b * NS + s0 + sl) * NF + f0 + tx];
    }
    __syncthreads();
#pragma unroll
    for (int r = 0; r < 4; ++r) {
        int fl = ty + r * 8;
        float v = t[tx][fl];
        __nv_bfloat16 h = __float2bfloat16_rn(v);
        float l = v - __bfloat162float(h);
        size_t idx = ((size_t)b * NF + f0 + fl) * NS + s0 + tx;
        g_vth[idx] = h;
        g_vtl[idx] = __float2bfloat16_rn(l);
    }
}

// ---------------------------------------------------------------------------
// Kernel 3: mma.sync (bf16 HMMA) fused attention, cp.async pipelined.
// Per tile: next-K cp.async issued after P-store barrier (overlaps PV MMA;
// K has no phase-B readers), next-V issued after phase-B barrier (overlaps
// next tile's mask LDGs).  Fragment/epilogue logic unchanged from R8.
// ---------------------------------------------------------------------------
#define QKW      132   /* uint32 words per Q/K row: (256+8 pad) bf16 */
#define VPW      36    /* uint32 words per VT/P row: (64+8 pad) bf16 */
#define QH_OFF   0
#define QL_OFF   33792
#define KH_OFF   67584
#define KL_OFF   101376
#define VTH_OFF  135168
#define VTL_OFF  172032
#define PH_OFF   208896
#define PL_OFF   218112
#define DEN_OFF  227328
#define ASMEM    227840

__global__ __launch_bounds__(256, 1) void attn_mma(
    const float* __restrict__ cmask,
    const int*   __restrict__ causality,
    float* __restrict__ out)
{
    extern __shared__ char smem[];
    const uint32_t sb = smem_u32(smem);
    const int tid = threadIdx.x;
    const int wid = tid >> 5, lane = tid & 31;
    const int wr = wid & 3, wc = wid >> 2;   // q-band, f-half
    const int g = lane >> 2, t4 = lane & 3;  // fragment row, quad index
    const int b = blockIdx.y;
    const int causal = causality[0];

    const uint32_t* Qh32 = (const uint32_t*)(smem + QH_OFF);
    const uint32_t* Ql32 = (const uint32_t*)(smem + QL_OFF);
    const uint32_t* Kh32 = (const uint32_t*)(smem + KH_OFF);
    const uint32_t* Kl32 = (const uint32_t*)(smem + KL_OFF);
    const uint32_t* Vh32 = (const uint32_t*)(smem + VTH_OFF);
    const uint32_t* Vl32 = (const uint32_t*)(smem + VTL_OFF);
    const uint32_t* Ph32 = (const uint32_t*)(smem + PH_OFF);
    const uint32_t* Pl32 = (const uint32_t*)(smem + PL_OFF);
    float* den_s = (float*)(smem + DEN_OFF);

    const int ar0 = (16 * wr + g) * QKW;
    const int ar1 = (16 * wr + g + 8) * QKW;
    const int pr0 = (16 * wr + g) * VPW;
    const int pr1 = (16 * wr + g + 8) * VPW;

    // cp.async staging: 8 iters x 2 copies each
    auto stage_K = [&](int k0) {
        const __nv_bfloat16* kh = g_kh + ((size_t)b * NS + k0) * NDK;
        const __nv_bfloat16* kl = g_kl + ((size_t)b * NS + k0) * NDK;
        for (int i = tid; i < 2048; i += 256) {
            int row = i >> 5, c8 = (i & 31) << 3;
            uint32_t off = (uint32_t)(row * (QKW * 2) + c8) * 2;
            CP16(sb + KH_OFF + off, kh + (size_t)row * NDK + c8);
            CP16(sb + KL_OFF + off, kl + (size_t)row * NDK + c8);
        }
    };
    auto stage_V = [&](int k0) {
        const __nv_bfloat16* vh = g_vth + (size_t)b * NF * NS + k0;
        const __nv_bfloat16* vl = g_vtl + (size_t)b * NF * NS + k0;
        for (int i = tid; i < 2048; i += 256) {
            int f = i >> 3, k8 = (i & 7) << 3;
            uint32_t off = (uint32_t)(f * (VPW * 2) + k8) * 2;
            CP16(sb + VTH_OFF + off, vh + (size_t)f * NS + k8);
            CP16(sb + VTL_OFF + off, vl + (size_t)f * NS + k8);
        }
    };

    for (int half = 0; half < 2; ++half) {
        const int qt = half ? (31 - (int)blockIdx.x) : (int)blockIdx.x;
        const int q0 = qt * 64;

        __syncthreads();  // previous half fully done before Q restage

        {
            const __nv_bfloat16* qh = g_qh + ((size_t)b * NS + q0) * NDK;
            const __nv_bfloat16* ql = g_ql + ((size_t)b * NS + q0) * NDK;
            for (int i = tid; i < 2048; i += 256) {
                int row = i >> 5, c8 = (i & 31) << 3;
                uint32_t off = (uint32_t)(row * (QKW * 2) + c8) * 2;
                *(uint4*)(smem + QH_OFF + off) = *(const uint4*)(qh + (size_t)row * NDK + c8);
                *(uint4*)(smem + QL_OFF + off) = *(const uint4*)(ql + (size_t)row * NDK + c8);
            }
        }

        float o[16][4];
#pragma unroll
        for (int j = 0; j < 16; ++j)
#pragma unroll
            for (int u = 0; u < 4; ++u) o[j][u] = 0.f;
        float denA = 0.f, denB = 0.f;

        const int kt0 = causal ? qt : 0;

        // prologue: stage first tile
        stage_K(kt0 * 64);
        stage_V(kt0 * 64);
        CP_COMMIT();

        for (int kt = kt0; kt < 32; ++kt) {
            const int k0 = kt * 64;

            // mask bits (overlaps in-flight cp.async)
            uint32_t mbits = 0;
            {
                const int q1 = q0 + 16 * wr + g;
                const int q2 = q1 + 8;
                const int kbase = k0 + 32 * wc + 2 * t4;
                const float* m1p = cmask + ((size_t)b * NS + q1) * NS;
                const float* m2p = cmask + ((size_t)b * NS + q2) * NS;
#pragma unroll
                for (int j = 0; j < 4; ++j) {
                    int kg = kbase + 8 * j;
                    float2 m1 = *(const float2*)(m1p + kg);
                    float2 m2 = *(const float2*)(m2p + kg);
                    uint32_t bits = 0;
                    if (m1.x > 0.f && (!causal || kg     >= q1)) bits |= 1u;
                    if (m1.y > 0.f && (!causal || kg + 1 >= q1)) bits |= 2u;
                    if (m2.x > 0.f && (!causal || kg     >= q2)) bits |= 4u;
                    if (m2.y > 0.f && (!causal || kg + 1 >= q2)) bits |= 8u;
                    mbits |= bits << (4 * j);
                }
            }

            CP_WAIT_ALL();
            __syncthreads();  // K/V (and Q on first iter) visible

            // ---- Phase A: S = Q K^T (3 bf16 splits)
            float s[4][4];
#pragma unroll
            for (int j = 0; j < 4; ++j)
#pragma unroll
                for (int u = 0; u < 4; ++u) s[j][u] = 0.f;

#pragma unroll 4
            for (int ks = 0; ks < 16; ++ks) {
                const int kw = ks * 8 + t4;
                uint32_t ah[4], al[4];
                ah[0] = Qh32[ar0 + kw];     ah[1] = Qh32[ar1 + kw];
                ah[2] = Qh32[ar0 + kw + 4]; ah[3] = Qh32[ar1 + kw + 4];
                al[0] = Ql32[ar0 + kw];     al[1] = Ql32[ar1 + kw];
                al[2] = Ql32[ar0 + kw + 4]; al[3] = Ql32[ar1 + kw + 4];
#pragma unroll
                for (int jp = 0; jp < 2; ++jp) {
                    const int br0 = (32 * wc + 16 * jp + g) * QKW;
                    const int br1 = (32 * wc + 16 * jp + 8 + g) * QKW;
                    uint32_t bh0 = Kh32[br0 + kw], bh1 = Kh32[br0 + kw + 4];
                    uint32_t bh2 = Kh32[br1 + kw], bh3 = Kh32[br1 + kw + 4];
                    uint32_t bl0 = Kl32[br0 + kw], bl1 = Kl32[br0 + kw + 4];
                    uint32_t bl2 = Kl32[br1 + kw], bl3 = Kl32[br1 + kw + 4];
                    mma_bf16(s[2 * jp],     ah, bh0, bh1);
                    mma_bf16(s[2 * jp],     al, bh0, bh1);
                    mma_bf16(s[2 * jp],     ah, bl0, bl1);
                    mma_bf16(s[2 * jp + 1], ah, bh2, bh3);
                    mma_bf16(s[2 * jp + 1], al, bh2, bh3);
                    mma_bf16(s[2 * jp + 1], ah, bl2, bl3);
                }
            }

            // ---- epilogue: p = exp(min(s/16,10)) masked; den; P hi/lo -> SMEM
            {
#pragma unroll
                for (int j = 0; j < 4; ++j) {
                    uint32_t bb = mbits >> (4 * j);
                    float p0 = (bb & 1u) ? __expf(fminf(s[j][0] * 0.0625f, 10.f)) : 0.f;
                    float p1 = (bb & 2u) ? __expf(fminf(s[j][1] * 0.0625f, 10.f)) : 0.f;
                    float p2 = (bb & 4u) ? __expf(fminf(s[j][2] * 0.0625f, 10.f)) : 0.f;
                    float p3 = (bb & 8u) ? __expf(fminf(s[j][3] * 0.0625f, 10.f)) : 0.f;
                    denA += p0 + p1;
                    denB += p2 + p3;
                    uint32_t lo1, lo2;
                    uint32_t hi1 = pack_hi2(p0, p1, lo1);
                    uint32_t hi2 = pack_hi2(p2, p3, lo2);
                    int col = 32 * wc + 2 * t4 + 8 * j;
                    uint32_t w1 = (uint32_t)((16 * wr + g) * VPW + (col >> 1));
                    uint32_t w2 = (uint32_t)((16 * wr + g + 8) * VPW + (col >> 1));
                    ((uint32_t*)(smem + PH_OFF))[w1] = hi1;
                    ((uint32_t*)(smem + PL_OFF))[w1] = lo1;
                    ((uint32_t*)(smem + PH_OFF))[w2] = hi2;
                    ((uint32_t*)(smem + PL_OFF))[w2] = lo2;
                }
            }
            __syncthreads();  // P visible; all warps done with K (phase A)

            // prefetch next tile's K — overlaps all of phase B
            if (kt + 1 < 32) { stage_K(k0 + 64); CP_COMMIT(); }

            // ---- Phase B: O += P V^T (3 bf16 splits)
#pragma unroll
            for (int ks = 0; ks < 4; ++ks) {
                const int kw = ks * 8 + t4;
                uint32_t ah[4], al[4];
                ah[0] = Ph32[pr0 + kw];     ah[1] = Ph32[pr1 + kw];
                ah[2] = Ph32[pr0 + kw + 4]; ah[3] = Ph32[pr1 + kw + 4];
                al[0] = Pl32[pr0 + kw];     al[1] = Pl32[pr1 + kw];
                al[2] = Pl32[pr0 + kw + 4]; al[3] = Pl32[pr1 + kw + 4];
#pragma unroll
                for (int jp = 0; jp < 8; ++jp) {
                    const int vr0 = (128 * wc + 16 * jp + g) * VPW;
                    const int vr1 = (128 * wc + 16 * jp + 8 + g) * VPW;
                    uint32_t bh0 = Vh32[vr0 + kw], bh1 = Vh32[vr0 + kw + 4];
                    uint32_t bh2 = Vh32[vr1 + kw], bh3 = Vh32[vr1 + kw + 4];
                    uint32_t bl0 = Vl32[vr0 + kw], bl1 = Vl32[vr0 + kw + 4];
                    uint32_t bl2 = Vl32[vr1 + kw], bl3 = Vl32[vr1 + kw + 4];
                    mma_bf16(o[2 * jp],     ah, bh0, bh1);
                    mma_bf16(o[2 * jp],     al, bh0, bh1);
                    mma_bf16(o[2 * jp],     ah, bl0, bl1);
                    mma_bf16(o[2 * jp + 1], ah, bh2, bh3);
                    mma_bf16(o[2 * jp + 1], al, bh2, bh3);
                    mma_bf16(o[2 * jp + 1], ah, bl2, bl3);
                }
            }
            __syncthreads();  // all warps done with V (phase B) and P

            // prefetch next tile's V — overlaps next tile's mask loads
            if (kt + 1 < 32) { stage_V(k0 + 64); CP_COMMIT(); }
        }

        denA += __shfl_xor_sync(0xffffffffu, denA, 1);
        denA += __shfl_xor_sync(0xffffffffu, denA, 2);
        denB += __shfl_xor_sync(0xffffffffu, denB, 1);
        denB += __shfl_xor_sync(0xffffffffu, denB, 2);
        __syncthreads();
        if (t4 == 0) {
            den_s[wc * 64 + 16 * wr + g] = denA;
            den_s[wc * 64 + 16 * wr + g + 8] = denB;
        }
        __syncthreads();

        {
            const int q1row = 16 * wr + g;
            const float inv1 = 1.0f / (den_s[q1row] + den_s[64 + q1row]);
            const float inv2 = 1.0f / (den_s[q1row + 8] + den_s[64 + q1row + 8]);
            float* o1 = out + ((size_t)b * NS + q0 + q1row) * NF;
            float* o2 = out + ((size_t)b * NS + q0 + q1row + 8) * NF;
#pragma unroll
            for (int j2 = 0; j2 < 16; ++j2) {
                int f = 128 * wc + 8 * j2 + 2 * t4;
                float2 v1, v2;
                v1.x = o[j2][0] * inv1; v1.y = o[j2][1] * inv1;
                v2.x = o[j2][2] * inv2; v2.y = o[j2][3] * inv2;
                *(float2*)(o1 + f) = v1;
                *(float2*)(o2 + f) = v2;
            }
        }
    }
}

// ---------------------------------------------------------------------------
extern "C" void kernel_launch(void* const* d_in, const int* in_sizes, int n_in,
                              void* d_out, int out_size)
{
    const float* seq  = (const float*)d_in[0];
    const float* pos  = (const float*)d_in[1];
    const float* tim  = (const float*)d_in[2];
    const float* Wq   = (const float*)d_in[3];
    const float* Wk   = (const float*)d_in[4];
    const float* cm   = (const float*)d_in[5];
    const int*   caus = (const int*)d_in[6];
    float* out = (float*)d_out;

    cudaFuncSetAttribute(proj_mma, cudaFuncAttributeMaxDynamicSharedMemorySize, PSMEM);
    cudaFuncSetAttribute(attn_mma, cudaFuncAttributeMaxDynamicSharedMemorySize, ASMEM);

    dim3 gp(NB * NS / 128, NDK / 128, 2);   // (128, 2, 2) = 512 CTAs
    proj_mma<<<gp, 256, PSMEM>>>(seq, pos, tim, Wq, Wk);

    dim3 gv(NS / 32, NF / 32, NB);
    vsplit_kernel<<<gv, dim3(32, 8)>>>(seq);

    dim3 ga(16, NB);   // 128 CTAs, 33 key-tiles each (causal), 1 wave
    attn_mma<<<ga, 256, ASMEM>>>(cm, caus, out);
}